// round 3
// baseline (speedup 1.0000x reference)
#include <cuda_runtime.h>
#include <math.h>
#include <stdint.h>

// ---------------- problem constants ----------------
#define BATCH 32
#define SEQ   256
#define DIM   512
#define PD    588      // 3*14*14
#define TOK   (BATCH*SEQ)   // 8192
#define NHEAD 8
#define HD    64
#define NEXP  8
#define HID   2048
#define ACAP  (TOK*2 + NEXP*64)   // 16896 padded assignment capacity
#define MAXT  (ACAP/64)           // 264 row tiles

// output layout: logits[32*512], fv[32*512], loss[1], attn_w[32*256*256]
#define OFF_FV    (BATCH*DIM)
#define OFF_LOSS  (2*BATCH*DIM)
#define OFF_ATTN  (2*BATCH*DIM + 1)

// ---------------- scratch ----------------
__device__ float g_patches[(size_t)TOK*PD];
__device__ float g_e[(size_t)TOK*DIM];
__device__ float g_xln[(size_t)TOK*DIM];
__device__ float g_q[(size_t)TOK*DIM];
__device__ float g_kk[(size_t)TOK*DIM];
__device__ float g_v[(size_t)TOK*DIM];
__device__ float g_attn[(size_t)BATCH*NHEAD*SEQ*SEQ];
__device__ float g_attout[(size_t)TOK*DIM];
__device__ float g_e2[(size_t)TOK*DIM];
__device__ float g_o1[(size_t)TOK*DIM];
__device__ float g_o2[(size_t)TOK*DIM];
__device__ float g_hidden[(size_t)ACAP*HID];
__device__ float g_contrib[(size_t)ACAP*DIM];
__device__ int   g_topi[TOK*2];
__device__ float g_topv[TOK*2];
__device__ int   g_counts[NEXP];
__device__ int   g_fill[NEXP];
__device__ int   g_off[NEXP+1];
__device__ int   g_tile_expert[MAXT];
__device__ int   g_assign_token[ACAP];
__device__ float g_assign_gate[ACAP];
__device__ int   g_token_slot[TOK*2];
__device__ float g_probsum[NEXP];
__device__ float g_fv[BATCH*DIM];
__device__ float g_loss[1];

// ---------------- small kernels ----------------
__global__ void zero_loss_kernel() { g_loss[0] = 0.f; }

__global__ void patch_kernel(const float* __restrict__ x) {
    int idx = blockIdx.x * 256 + threadIdx.x;
    if (idx >= TOK * PD) return;
    int token = idx / PD;
    int p = idx - token * PD;
    int b = token >> 8;
    int s = token & 255;
    int hr = s >> 4, wc = s & 15;
    int c  = p % 3;
    int pq = p / 3;          // p1*14+p2
    int p2 = pq % 14, p1 = pq / 14;
    g_patches[idx] = x[(((size_t)(b*3 + c)*224) + hr*14 + p1)*224 + wc*14 + p2];
}

__global__ void ln_kernel(const float* __restrict__ x, const float* __restrict__ g,
                          const float* __restrict__ b, float* __restrict__ y) {
    int row = blockIdx.x;
    const float* xr = x + (size_t)row * DIM;
    int t = threadIdx.x;        // 256 threads, 2 elems each
    float v0 = xr[t], v1 = xr[t + 256];
    __shared__ float s1[256], s2[256];
    s1[t] = v0 + v1;
    s2[t] = v0*v0 + v1*v1;
    __syncthreads();
    for (int s = 128; s; s >>= 1) {
        if (t < s) { s1[t] += s1[t+s]; s2[t] += s2[t+s]; }
        __syncthreads();
    }
    float m   = s1[0] * (1.f/512.f);
    float var = s2[0] * (1.f/512.f) - m*m;
    float r   = rsqrtf(var + 1e-5f);
    y[(size_t)row*DIM + t]       = (v0 - m) * r * g[t]     + b[t];
    y[(size_t)row*DIM + t + 256] = (v1 - m) * r * g[t+256] + b[t+256];
}

// ---------------- generic SGEMM: C = A[M,K]@B[K,N] + bias (+res)(+pos) ----------------
__global__ void __launch_bounds__(256)
sgemm_kernel(const float* __restrict__ A, const float* __restrict__ Bm,
             const float* __restrict__ bias, const float* __restrict__ res,
             const float* __restrict__ pos, float* __restrict__ C,
             int M, int N, int K) {
    __shared__ float As[16][65];
    __shared__ float Bs[16][65];
    int tid = threadIdx.x;
    int ty = tid >> 4, tx = tid & 15;
    int m0 = blockIdx.y * 64, n0 = blockIdx.x * 64;
    int ar = tid >> 2, ac = (tid & 3) << 2;
    int br = tid >> 4, bc = (tid & 15) << 2;
    float acc[4][4] = {};
    for (int k0 = 0; k0 < K; k0 += 16) {
        #pragma unroll
        for (int u = 0; u < 4; u++) {
            int k = k0 + ac + u;
            As[ac+u][ar] = (m0 + ar < M && k < K) ? A[(size_t)(m0+ar)*K + k] : 0.f;
        }
        #pragma unroll
        for (int u = 0; u < 4; u++) {
            int k = k0 + br, n = n0 + bc + u;
            Bs[br][bc+u] = (k < K && n < N) ? Bm[(size_t)k*N + n] : 0.f;
        }
        __syncthreads();
        #pragma unroll
        for (int kx = 0; kx < 16; kx++) {
            float a[4], bb[4];
            #pragma unroll
            for (int i = 0; i < 4; i++) a[i]  = As[kx][ty*4+i];
            #pragma unroll
            for (int j = 0; j < 4; j++) bb[j] = Bs[kx][tx*4+j];
            #pragma unroll
            for (int i = 0; i < 4; i++)
                #pragma unroll
                for (int j = 0; j < 4; j++)
                    acc[i][j] += a[i]*bb[j];
        }
        __syncthreads();
    }
    #pragma unroll
    for (int i = 0; i < 4; i++) {
        int m = m0 + ty*4 + i;
        if (m >= M) continue;
        #pragma unroll
        for (int j = 0; j < 4; j++) {
            int n = n0 + tx*4 + j;
            if (n >= N) continue;
            float v = acc[i][j] + bias[n];
            if (res) v += res[(size_t)m*N + n];
            if (pos) v += pos[(size_t)(m & 255)*N + n];
            C[(size_t)m*N + n] = v;
        }
    }
}

// ---------------- attention ----------------
__global__ void __launch_bounds__(256)
scores_kernel() {
    int bh = blockIdx.z;
    int b = bh >> 3, h = bh & 7;
    const float* Q = g_q  + (size_t)(b*SEQ)*DIM + h*HD;
    const float* K = g_kk + (size_t)(b*SEQ)*DIM + h*HD;
    __shared__ float Qs[64][65], Ks[64][65];
    int tid = threadIdx.x;
    int i0 = blockIdx.x * 64, j0 = blockIdx.y * 64;
    for (int idx = tid; idx < 64*64; idx += 256) {
        int r = idx >> 6, c = idx & 63;
        Qs[r][c] = Q[(size_t)(i0+r)*DIM + c];
        Ks[r][c] = K[(size_t)(j0+r)*DIM + c];
    }
    __syncthreads();
    int ty = tid >> 4, tx = tid & 15;
    float acc[4][4] = {};
    #pragma unroll 8
    for (int kx = 0; kx < 64; kx++) {
        float a[4], bb[4];
        #pragma unroll
        for (int i = 0; i < 4; i++) a[i]  = Qs[ty*4+i][kx];
        #pragma unroll
        for (int j = 0; j < 4; j++) bb[j] = Ks[tx*4+j][kx];
        #pragma unroll
        for (int i = 0; i < 4; i++)
            #pragma unroll
            for (int j = 0; j < 4; j++)
                acc[i][j] += a[i]*bb[j];
    }
    float* Cp = g_attn + (size_t)bh*SEQ*SEQ;
    #pragma unroll
    for (int i = 0; i < 4; i++)
        #pragma unroll
        for (int j = 0; j < 4; j++)
            Cp[(size_t)(i0+ty*4+i)*SEQ + (j0+tx*4+j)] = acc[i][j] * 0.125f;
}

__global__ void softmax256_kernel() {
    float* row = g_attn + (size_t)blockIdx.x * 256;
    int t = threadIdx.x;
    float v = row[t];
    __shared__ float red[256];
    red[t] = v; __syncthreads();
    for (int s = 128; s; s >>= 1) { if (t < s) red[t] = fmaxf(red[t], red[t+s]); __syncthreads(); }
    float mx = red[0]; __syncthreads();
    float e = expf(v - mx);
    red[t] = e; __syncthreads();
    for (int s = 128; s; s >>= 1) { if (t < s) red[t] += red[t+s]; __syncthreads(); }
    row[t] = e / red[0];
}

__global__ void attn_mean_sm_kernel(float* __restrict__ out) {
    int bs = blockIdx.x;        // b*256 + s
    int b = bs >> 8, srow = bs & 255;
    int j = threadIdx.x;
    float v = 0.f;
    #pragma unroll
    for (int h = 0; h < NHEAD; h++)
        v += g_attn[((size_t)(b*NHEAD + h)*SEQ + srow)*SEQ + j];
    v *= (1.f / NHEAD);
    __shared__ float red[256];
    red[j] = v; __syncthreads();
    for (int s = 128; s; s >>= 1) { if (j < s) red[j] = fmaxf(red[j], red[j+s]); __syncthreads(); }
    float mx = red[0]; __syncthreads();
    float e = expf(v - mx);
    red[j] = e; __syncthreads();
    for (int s = 128; s; s >>= 1) { if (j < s) red[j] += red[j+s]; __syncthreads(); }
    out[(size_t)bs*256 + j] = e / red[0];
}

__global__ void __launch_bounds__(256)
attnv_kernel() {
    int bh = blockIdx.z;
    int b = bh >> 3, h = bh & 7;
    const float* Ap = g_attn + (size_t)bh*SEQ*SEQ;
    const float* V  = g_v + (size_t)(b*SEQ)*DIM + h*HD;
    int i0 = blockIdx.x * 64;
    __shared__ float As[64][65], Vs[64][65];
    int tid = threadIdx.x;
    int ty = tid >> 4, tx = tid & 15;
    float acc[4][4] = {};
    for (int c0 = 0; c0 < SEQ; c0 += 64) {
        for (int idx = tid; idx < 64*64; idx += 256) {
            int r = idx >> 6, c = idx & 63;
            As[r][c] = Ap[(size_t)(i0+r)*SEQ + c0 + c];
            Vs[r][c] = V[(size_t)(c0+r)*DIM + c];
        }
        __syncthreads();
        #pragma unroll 8
        for (int kx = 0; kx < 64; kx++) {
            float a[4], bb[4];
            #pragma unroll
            for (int i = 0; i < 4; i++) a[i]  = As[ty*4+i][kx];
            #pragma unroll
            for (int j = 0; j < 4; j++) bb[j] = Vs[kx][tx*4+j];
            #pragma unroll
            for (int i = 0; i < 4; i++)
                #pragma unroll
                for (int j = 0; j < 4; j++)
                    acc[i][j] += a[i]*bb[j];
        }
        __syncthreads();
    }
    #pragma unroll
    for (int i = 0; i < 4; i++)
        #pragma unroll
        for (int j = 0; j < 4; j++)
            g_attout[(size_t)(b*SEQ + i0 + ty*4 + i)*DIM + h*HD + tx*4 + j] = acc[i][j];
}

// ---------------- MoE ----------------
__global__ void moe_reset_kernel() {
    int idx = blockIdx.x * 256 + threadIdx.x;
    if (idx < ACAP) g_assign_token[idx] = -1;
    if (idx < NEXP) { g_counts[idx] = 0; g_fill[idx] = 0; g_probsum[idx] = 0.f; }
}

__global__ void router_kernel(const float* __restrict__ x, const float* __restrict__ rw,
                              const float* __restrict__ rb) {
    __shared__ float s_ps[NEXP];
    __shared__ int   s_cnt[NEXP];
    int t = threadIdx.x;
    if (t < NEXP) { s_ps[t] = 0.f; s_cnt[t] = 0; }
    __syncthreads();
    int warp = t >> 5, lane = t & 31;
    int token = blockIdx.x * 8 + warp;
    float acc[NEXP] = {};
    const float* xr = x + (size_t)token * DIM;
    for (int kx = lane; kx < DIM; kx += 32) {
        float xv = xr[kx];
        const float* rr = rw + (size_t)kx * NEXP;
        #pragma unroll
        for (int e = 0; e < NEXP; e++) acc[e] += xv * rr[e];
    }
    #pragma unroll
    for (int e = 0; e < NEXP; e++)
        #pragma unroll
        for (int o = 16; o; o >>= 1)
            acc[e] += __shfl_down_sync(0xffffffffu, acc[e], o);
    if (lane == 0) {
        float p[NEXP], mx = -1e30f;
        #pragma unroll
        for (int e = 0; e < NEXP; e++) { acc[e] += rb[e]; mx = fmaxf(mx, acc[e]); }
        float sum = 0.f;
        #pragma unroll
        for (int e = 0; e < NEXP; e++) { p[e] = expf(acc[e] - mx); sum += p[e]; }
        float inv = 1.f / sum;
        #pragma unroll
        for (int e = 0; e < NEXP; e++) p[e] *= inv;
        int i1 = 0;
        #pragma unroll
        for (int e = 1; e < NEXP; e++) if (p[e] > p[i1]) i1 = e;
        int i2 = (i1 == 0) ? 1 : 0;
        #pragma unroll
        for (int e = 0; e < NEXP; e++) if (e != i1 && p[e] > p[i2]) i2 = e;
        g_topi[token*2]   = i1; g_topv[token*2]   = p[i1];
        g_topi[token*2+1] = i2; g_topv[token*2+1] = p[i2];
        atomicAdd(&s_cnt[i1], 1);
        atomicAdd(&s_cnt[i2], 1);
        #pragma unroll
        for (int e = 0; e < NEXP; e++) atomicAdd(&s_ps[e], p[e]);
    }
    __syncthreads();
    if (t < NEXP) {
        atomicAdd(&g_counts[t], s_cnt[t]);
        atomicAdd(&g_probsum[t], s_ps[t]);
    }
}

__global__ void loss_accum_kernel() {
    float L = 0.f;
    for (int e = 0; e < NEXP; e++)
        L += ((float)g_counts[e] / (float)TOK) * (g_probsum[e] / (float)TOK);
    g_loss[0] += (float)NEXP * L;
}

__global__ void bucket_prep_kernel() {
    if (threadIdx.x == 0) {
        int off = 0;
        for (int e = 0; e < NEXP; e++) {
            g_off[e] = off;
            off += ((g_counts[e] + 63) >> 6) << 6;
        }
        g_off[NEXP] = off;
    }
    __syncthreads();
    for (int tix = threadIdx.x; tix < MAXT; tix += blockDim.x) {
        int e = -1;
        for (int q = 0; q < NEXP; q++)
            if (tix*64 >= g_off[q] && tix*64 < g_off[q+1]) e = q;
        g_tile_expert[tix] = e;
    }
}

__global__ void scatter_kernel() {
    int token = blockIdx.x * 256 + threadIdx.x;
    if (token >= TOK) return;
    #pragma unroll
    for (int kk = 0; kk < 2; kk++) {
        int e = g_topi[token*2 + kk];
        int p = atomicAdd(&g_fill[e], 1);
        int slot = g_off[e] + p;
        g_assign_token[slot] = token;
        g_assign_gate[slot]  = g_topv[token*2 + kk];
        g_token_slot[token*2 + kk] = slot;
    }
}

__global__ void __launch_bounds__(256)
moe_up_kernel(const float* __restrict__ X, const float* __restrict__ w1,
              const float* __restrict__ b1) {
    int tile = blockIdx.y;
    int e = g_tile_expert[tile];
    if (e < 0) return;
    __shared__ float As[16][65], Bs[16][65];
    __shared__ int s_tok[64];
    int tid = threadIdx.x;
    if (tid < 64) s_tok[tid] = g_assign_token[tile*64 + tid];
    __syncthreads();
    const float* W = w1 + (size_t)e * DIM * HID;
    int n0 = blockIdx.x * 64;
    int ty = tid >> 4, tx = tid & 15;
    int ar = tid >> 2, ac = (tid & 3) << 2;
    int br = tid >> 4, bc = (tid & 15) << 2;
    int tokA = s_tok[ar];
    const float* xrow = (tokA >= 0) ? X + (size_t)tokA * DIM : nullptr;
    float acc[4][4] = {};
    for (int k0 = 0; k0 < DIM; k0 += 16) {
        #pragma unroll
        for (int u = 0; u < 4; u++)
            As[ac+u][ar] = xrow ? xrow[k0 + ac + u] : 0.f;
        #pragma unroll
        for (int u = 0; u < 4; u++)
            Bs[br][bc+u] = W[(size_t)(k0 + br) * HID + n0 + bc + u];
        __syncthreads();
        #pragma unroll
        for (int kx = 0; kx < 16; kx++) {
            float a[4], bb[4];
            #pragma unroll
            for (int i = 0; i < 4; i++) a[i]  = As[kx][ty*4+i];
            #pragma unroll
            for (int j = 0; j < 4; j++) bb[j] = Bs[kx][tx*4+j];
            #pragma unroll
            for (int i = 0; i < 4; i++)
                #pragma unroll
                for (int j = 0; j < 4; j++)
                    acc[i][j] += a[i]*bb[j];
        }
        __syncthreads();
    }
    #pragma unroll
    for (int i = 0; i < 4; i++) {
        int row = ty*4 + i;
        if (s_tok[row] < 0) continue;
        #pragma unroll
        for (int j = 0; j < 4; j++) {
            int n = n0 + tx*4 + j;
            float v = acc[i][j] + b1[(size_t)e*HID + n];
            v = 0.5f * v * (1.f + erff(v * 0.70710678118654752f));   // exact GELU
            g_hidden[(size_t)(tile*64 + row)*HID + n] = v;
        }
    }
}

__global__ void __launch_bounds__(256)
moe_down_kernel(const float* __restrict__ w2, const float* __restrict__ b2) {
    int tile = blockIdx.y;
    int e = g_tile_expert[tile];
    if (e < 0) return;
    __shared__ float As[16][65], Bs[16][65];
    __shared__ int   s_tok[64];
    __shared__ float s_gate[64];
    int tid = threadIdx.x;
    if (tid < 64) {
        s_tok[tid]  = g_assign_token[tile*64 + tid];
        s_gate[tid] = g_assign_gate[tile*64 + tid];
    }
    __syncthreads();
    const float* W = w2 + (size_t)e * HID * DIM;
    const float* Hrow = g_hidden + (size_t)tile * 64 * HID;
    int n0 = blockIdx.x * 64;
    int ty = tid >> 4, tx = tid & 15;
    int ar = tid >> 2, ac = (tid & 3) << 2;
    int br = tid >> 4, bc = (tid & 15) << 2;
    float acc[4][4] = {};
    for (int k0 = 0; k0 < HID; k0 += 16) {
        #pragma unroll
        for (int u = 0; u < 4; u++)
            As[ac+u][ar] = Hrow[(size_t)ar*HID + k0 + ac + u];
        #pragma unroll
        for (int u = 0; u < 4; u++)
            Bs[br][bc+u] = W[(size_t)(k0 + br)*DIM + n0 + bc + u];
        __syncthreads();
        #pragma unroll
        for (int kx = 0; kx < 16; kx++) {
            float a[4], bb[4];
            #pragma unroll
            for (int i = 0; i < 4; i++) a[i]  = As[kx][ty*4+i];
            #pragma unroll
            for (int j = 0; j < 4; j++) bb[j] = Bs[kx][tx*4+j];
            #pragma unroll
            for (int i = 0; i < 4; i++)
                #pragma unroll
                for (int j = 0; j < 4; j++)
                    acc[i][j] += a[i]*bb[j];
        }
        __syncthreads();
    }
    #pragma unroll
    for (int i = 0; i < 4; i++) {
        int row = ty*4 + i;
        if (s_tok[row] < 0) continue;
        float gate = s_gate[row];
        #pragma unroll
        for (int j = 0; j < 4; j++) {
            int n = n0 + tx*4 + j;
            g_contrib[(size_t)(tile*64 + row)*DIM + n] =
                (acc[i][j] + b2[(size_t)e*DIM + n]) * gate;
        }
    }
}

__global__ void moe_combine_kernel(float* __restrict__ o) {
    int i = blockIdx.x * 256 + threadIdx.x;     // < TOK*DIM
    int token = i >> 9, d = i & 511;
    int s0 = g_token_slot[token*2], s1 = g_token_slot[token*2 + 1];
    o[i] = g_contrib[(size_t)s0*DIM + d] + g_contrib[(size_t)s1*DIM + d];
}

// ---------------- head ----------------
__global__ void fv_kernel(const float* __restrict__ o2, float* __restrict__ out_fv) {
    int b = blockIdx.x, d = threadIdx.x;    // 512 threads
    float s = 0.f;
    for (int t = 0; t < SEQ; t++)
        s += o2[(size_t)(b*SEQ + t)*DIM + d];
    float v = s * (1.f / SEQ);
    out_fv[b*DIM + d] = v;
    g_fv[b*DIM + d] = v;
}

__global__ void logits_kernel(const float* __restrict__ cw, const float* __restrict__ cb,
                              float* __restrict__ out) {
    __shared__ float xf[DIM];
    int b = blockIdx.x, t = threadIdx.x;    // 512 threads
    xf[t] = g_fv[b*DIM + t];
    __syncthreads();
    float acc = 0.f;
    for (int kx = 0; kx < DIM; kx++)
        acc += xf[kx] * cw[(size_t)kx*DIM + t];
    out[b*DIM + t] = acc + cb[t];
}

__global__ void loss_write_kernel(float* __restrict__ dst) { dst[0] = g_loss[0]; }

// ---------------- host ----------------
static void run_moe(const float* xin, const float* rw, const float* rb,
                    const float* w1, const float* b1,
                    const float* w2, const float* b2, float* o) {
    moe_reset_kernel<<<(ACAP + 255)/256, 256>>>();
    router_kernel<<<TOK/8, 256>>>(xin, rw, rb);
    loss_accum_kernel<<<1, 1>>>();
    bucket_prep_kernel<<<1, 64>>>();
    scatter_kernel<<<TOK/256, 256>>>();
    moe_up_kernel<<<dim3(HID/64, MAXT), 256>>>(xin, w1, b1);
    moe_down_kernel<<<dim3(DIM/64, MAXT), 256>>>(w2, b2);
    moe_combine_kernel<<<TOK*DIM/256, 256>>>(o);
}

extern "C" void kernel_launch(void* const* d_in, const int* in_sizes, int n_in,
                              void* d_out, int out_size) {
    const float* x     = (const float*)d_in[0];
    const float* pe_w  = (const float*)d_in[1];
    const float* pe_b  = (const float*)d_in[2];
    const float* pos   = (const float*)d_in[3];
    const float* ln1_g = (const float*)d_in[4];
    const float* ln1_b = (const float*)d_in[5];
    const float* ln2_g = (const float*)d_in[6];
    const float* ln2_b = (const float*)d_in[7];
    const float* ln3_g = (const float*)d_in[8];
    const float* ln3_b = (const float*)d_in[9];
    const float* wq = (const float*)d_in[10];
    const float* bq = (const float*)d_in[11];
    const float* wk = (const float*)d_in[12];
    const float* bk = (const float*)d_in[13];
    const float* wv = (const float*)d_in[14];
    const float* bv = (const float*)d_in[15];
    const float* wo = (const float*)d_in[16];
    const float* bo = (const float*)d_in[17];
    const float* m1_rw = (const float*)d_in[18];
    const float* m1_rb = (const float*)d_in[19];
    const float* m1_w1 = (const float*)d_in[20];
    const float* m1_b1 = (const float*)d_in[21];
    const float* m1_w2 = (const float*)d_in[22];
    const float* m1_b2 = (const float*)d_in[23];
    const float* m2_rw = (const float*)d_in[24];
    const float* m2_rb = (const float*)d_in[25];
    const float* m2_w1 = (const float*)d_in[26];
    const float* m2_b1 = (const float*)d_in[27];
    const float* m2_w2 = (const float*)d_in[28];
    const float* m2_b2 = (const float*)d_in[29];
    const float* cls_w = (const float*)d_in[30];
    const float* cls_b = (const float*)d_in[31];
    float* out = (float*)d_out;

    float *p_patches, *p_e, *p_xln, *p_q, *p_k, *p_v, *p_attout, *p_e2, *p_o1, *p_o2;
    cudaGetSymbolAddress((void**)&p_patches, g_patches);
    cudaGetSymbolAddress((void**)&p_e,      g_e);
    cudaGetSymbolAddress((void**)&p_xln,    g_xln);
    cudaGetSymbolAddress((void**)&p_q,      g_q);
    cudaGetSymbolAddress((void**)&p_k,      g_kk);
    cudaGetSymbolAddress((void**)&p_v,      g_v);
    cudaGetSymbolAddress((void**)&p_attout, g_attout);
    cudaGetSymbolAddress((void**)&p_e2,     g_e2);
    cudaGetSymbolAddress((void**)&p_o1,     g_o1);
    cudaGetSymbolAddress((void**)&p_o2,     g_o2);

    zero_loss_kernel<<<1, 1>>>();

    // patch embed:  e = patches @ pe_w + pe_b + pos
    patch_kernel<<<(TOK*PD + 255)/256, 256>>>(x);
    dim3 gD(DIM/64, TOK/64);   // (8,128)
    sgemm_kernel<<<gD, 256>>>(p_patches, pe_w, pe_b, nullptr, pos, p_e, TOK, DIM, PD);

    // attention
    ln_kernel<<<TOK, 256>>>(p_e, ln1_g, ln1_b, p_xln);
    sgemm_kernel<<<gD, 256>>>(p_xln, wq, bq, nullptr, nullptr, p_q, TOK, DIM, DIM);
    sgemm_kernel<<<gD, 256>>>(p_xln, wk, bk, nullptr, nullptr, p_k, TOK, DIM, DIM);
    sgemm_kernel<<<gD, 256>>>(p_xln, wv, bv, nullptr, nullptr, p_v, TOK, DIM, DIM);
    scores_kernel<<<dim3(4, 4, BATCH*NHEAD), 256>>>();
    softmax256_kernel<<<BATCH*NHEAD*SEQ, 256>>>();
    attn_mean_sm_kernel<<<TOK, 256>>>(out + OFF_ATTN);
    attnv_kernel<<<dim3(4, 1, BATCH*NHEAD), 256>>>();
    sgemm_kernel<<<gD, 256>>>(p_attout, wo, bo, p_e, nullptr, p_e2, TOK, DIM, DIM);

    // MoE 1
    ln_kernel<<<TOK, 256>>>(p_e2, ln2_g, ln2_b, p_xln);
    run_moe(p_xln, m1_rw, m1_rb, m1_w1, m1_b1, m1_w2, m1_b2, p_o1);

    // MoE 2
    ln_kernel<<<TOK, 256>>>(p_o1, ln3_g, ln3_b, p_xln);
    run_moe(p_xln, m2_rw, m2_rb, m2_w1, m2_b1, m2_w2, m2_b2, p_o2);

    // head
    fv_kernel<<<BATCH, 512>>>(p_o2, out + OFF_FV);
    logits_kernel<<<BATCH, 512>>>(cls_w, cls_b, out);
    loss_write_kernel<<<1, 1>>>(out + OFF_LOSS);

    (void)in_sizes; (void)n_in; (void)out_size;
}

// round 7
// speedup vs baseline: 1.9326x; 1.9326x over previous
#include <cuda_runtime.h>
#include <math.h>
#include <stdint.h>

// ---------------- problem constants ----------------
#define BATCH 32
#define SEQ   256
#define DIM   512
#define PD    588      // 3*14*14
#define TOK   (BATCH*SEQ)   // 8192
#define NHEAD 8
#define HD    64
#define NEXP  8
#define HID   2048
#define ACAP  (TOK*2 + NEXP*128)   // 17408, 128-aligned expert segments
#define MAXT  (ACAP/128)           // 136 row tiles

// output layout: logits[32*512], fv[32*512], loss[1], attn_w[32*256*256]
#define OFF_FV    (BATCH*DIM)
#define OFF_LOSS  (2*BATCH*DIM)
#define OFF_ATTN  (2*BATCH*DIM + 1)

// gemm modes
#define GM_BIAS      0
#define GM_PATCH     1
#define GM_RES       2
#define GM_MOE_UP    3
#define GM_MOE_DOWN  4

// ---------------- scratch ----------------
__device__ float g_patches[(size_t)TOK*PD];
__device__ float g_e[(size_t)TOK*DIM];
__device__ float g_xln[(size_t)TOK*DIM];
__device__ float g_q[(size_t)TOK*DIM];
__device__ float g_kk[(size_t)TOK*DIM];
__device__ float g_v[(size_t)TOK*DIM];
__device__ float g_attn[(size_t)BATCH*NHEAD*SEQ*SEQ];
__device__ float g_attout[(size_t)TOK*DIM];
__device__ float g_e2[(size_t)TOK*DIM];
__device__ float g_o1[(size_t)TOK*DIM];
__device__ float g_o2[(size_t)TOK*DIM];
__device__ float g_hidden[(size_t)ACAP*HID];
__device__ float g_contrib[(size_t)ACAP*DIM];
__device__ int   g_topi[TOK*2];
__device__ float g_topv[TOK*2];
__device__ int   g_counts[NEXP];
__device__ int   g_fill[NEXP];
__device__ int   g_off[NEXP+1];
__device__ int   g_tile_expert[MAXT];
__device__ int   g_assign_token[ACAP];
__device__ float g_assign_gate[ACAP];
__device__ int   g_token_slot[TOK*2];
__device__ float g_probsum[NEXP];
__device__ float g_fv[BATCH*DIM];
__device__ float g_loss[1];

// ---------------- ptx helpers ----------------
__device__ __forceinline__ uint32_t cvt_tf32(float x) {
    uint32_t r; asm("cvt.rna.tf32.f32 %0, %1;" : "=r"(r) : "f"(x)); return r;
}
__device__ __forceinline__ void split_tf32(float x, uint32_t& hi, uint32_t& lo) {
    hi = cvt_tf32(x);
    lo = cvt_tf32(x - __uint_as_float(hi));
}
__device__ __forceinline__ uint32_t smem_u32(const void* p) {
    return (uint32_t)__cvta_generic_to_shared(p);
}
__device__ __forceinline__ void cp_async16(uint32_t dst, const void* src, int bytes) {
    asm volatile("cp.async.cg.shared.global [%0], [%1], 16, %2;\n"
                 :: "r"(dst), "l"(src), "r"(bytes));
}
__device__ __forceinline__ void cp_commit() { asm volatile("cp.async.commit_group;\n"); }
__device__ __forceinline__ void cp_wait1()  { asm volatile("cp.async.wait_group 1;\n"); }
__device__ __forceinline__ void cp_wait0()  { asm volatile("cp.async.wait_group 0;\n"); }

__device__ __forceinline__ void mma_tf32(float* c, const uint32_t* a, const uint32_t* b) {
    asm volatile("mma.sync.aligned.m16n8k8.row.col.f32.tf32.tf32.f32 "
                 "{%0,%1,%2,%3},{%4,%5,%6,%7},{%8,%9},{%0,%1,%2,%3};\n"
                 : "+f"(c[0]), "+f"(c[1]), "+f"(c[2]), "+f"(c[3])
                 : "r"(a[0]), "r"(a[1]), "r"(a[2]), "r"(a[3]), "r"(b[0]), "r"(b[1]));
}

// ---------------- small kernels ----------------
__global__ void zero_loss_kernel() { g_loss[0] = 0.f; }

__global__ void patch_kernel(const float* __restrict__ x) {
    int idx = blockIdx.x * 256 + threadIdx.x;
    if (idx >= TOK * PD) return;
    int token = idx / PD;
    int p = idx - token * PD;
    int b = token >> 8;
    int s = token & 255;
    int hr = s >> 4, wc = s & 15;
    int c  = p % 3;
    int pq = p / 3;          // p1*14+p2
    int p2 = pq % 14, p1 = pq / 14;
    g_patches[idx] = x[(((size_t)(b*3 + c)*224) + hr*14 + p1)*224 + wc*14 + p2];
}

__global__ void ln_kernel(const float* __restrict__ x, const float* __restrict__ g,
                          const float* __restrict__ b, float* __restrict__ y) {
    int row = blockIdx.x;
    const float* xr = x + (size_t)row * DIM;
    int t = threadIdx.x;        // 256 threads, 2 elems each
    float v0 = xr[t], v1 = xr[t + 256];
    __shared__ float s1[256], s2[256];
    s1[t] = v0 + v1;
    s2[t] = v0*v0 + v1*v1;
    __syncthreads();
    for (int s = 128; s; s >>= 1) {
        if (t < s) { s1[t] += s1[t+s]; s2[t] += s2[t+s]; }
        __syncthreads();
    }
    float m   = s1[0] * (1.f/512.f);
    float var = s2[0] * (1.f/512.f) - m*m;
    float r   = rsqrtf(var + 1e-5f);
    y[(size_t)row*DIM + t]       = (v0 - m) * r * g[t]     + b[t];
    y[(size_t)row*DIM + t + 256] = (v1 - m) * r * g[t+256] + b[t+256];
}

// ---------------- 3xTF32 tensor-core GEMM (fp32-accurate) ----------------
// C[M,N] = A[M,K] @ B[K,N] (+ epilogue per mode)
// Block tile 128x128, BK=16, 256 threads = 8 warps (4m x 2n), warp tile 32x64.
// 2-stage cp.async pipeline. Each operand split hi/lo in tf32; accumulate
// lo*hi + hi*lo + hi*hi (small terms first) -> ~2^-22 residual per product.
__global__ void __launch_bounds__(256)
gemm_tf32_kernel(const float* __restrict__ A, const float* __restrict__ Bbase,
                 const float* __restrict__ biasbase, const float* __restrict__ extra,
                 float* __restrict__ Cout, int N, int K, int mode)
{
    int tileY = blockIdx.y;
    const float* B = Bbase;
    const float* bias = biasbase;
    if (mode == GM_MOE_UP || mode == GM_MOE_DOWN) {
        int expert = g_tile_expert[tileY];
        if (expert < 0) return;
        B    = Bbase    + (size_t)expert * K * N;
        bias = biasbase + (size_t)expert * N;
    }

    __shared__ float As[2][128][20];    // [m][k], pad 4 -> conflict-free frags
    __shared__ float Bs[2][16][136];    // [k][n], pad 8 -> conflict-free frags

    int tid = threadIdx.x;
    int m_base = tileY * 128;
    int n_base = blockIdx.x * 128;

    // ---- A source: 2 rows per thread (r and r+64), one float4 column each
    int rA = tid >> 2, cA = (tid & 3) * 4;
    const float* aptr0; const float* aptr1;
    bool av0 = true, av1 = true;
    if (mode == GM_MOE_UP) {
        int t0 = g_assign_token[m_base + rA];
        int t1 = g_assign_token[m_base + rA + 64];
        av0 = (t0 >= 0); av1 = (t1 >= 0);
        aptr0 = A + (size_t)(av0 ? t0 : 0) * K + cA;
        aptr1 = A + (size_t)(av1 ? t1 : 0) * K + cA;
    } else {
        aptr0 = A + (size_t)(m_base + rA) * K + cA;
        aptr1 = A + (size_t)(m_base + rA + 64) * K + cA;
    }
    // ---- B source: 2 rows per thread (rB and rB+8), one float4 each
    int rB = tid >> 5;            // 0..7
    int cB = (tid & 31) * 4;      // 0..124
    const float* bptr0 = B + (size_t)rB * N + n_base + cB;
    const float* bptr1 = B + (size_t)(rB + 8) * N + n_base + cB;

    uint32_t sA0[2], sA1[2], sB0[2], sB1[2];
    #pragma unroll
    for (int bf = 0; bf < 2; bf++) {
        sA0[bf] = smem_u32(&As[bf][rA][cA]);
        sA1[bf] = smem_u32(&As[bf][rA + 64][cA]);
        sB0[bf] = smem_u32(&Bs[bf][rB][cB]);
        sB1[bf] = smem_u32(&Bs[bf][rB + 8][cB]);
    }

    int lane = tid & 31, warp = tid >> 5;
    int wm = warp >> 1, wn = warp & 1;
    int gid = lane >> 2, tig = lane & 3;

    float cacc[2][8][4];
    #pragma unroll
    for (int mt = 0; mt < 2; mt++)
        #pragma unroll
        for (int nt = 0; nt < 8; nt++)
            #pragma unroll
            for (int q = 0; q < 4; q++) cacc[mt][nt][q] = 0.f;

    int KT = (K + 15) / 16;

    // prologue: stage 0
    {
        int k0 = 0, bf = 0;
        cp_async16(sA0[bf], aptr0 + k0, (av0 && k0 + cA < K) ? 16 : 0);
        cp_async16(sA1[bf], aptr1 + k0, (av1 && k0 + cA < K) ? 16 : 0);
        cp_async16(sB0[bf], bptr0 + (size_t)k0 * N, (k0 + rB < K) ? 16 : 0);
        cp_async16(sB1[bf], bptr1 + (size_t)k0 * N, (k0 + rB + 8 < K) ? 16 : 0);
        cp_commit();
    }

    for (int it = 0; it < KT; ++it) {
        if (it + 1 < KT) {
            int k0 = (it + 1) * 16, bf = (it + 1) & 1;
            cp_async16(sA0[bf], aptr0 + k0, (av0 && k0 + cA < K) ? 16 : 0);
            cp_async16(sA1[bf], aptr1 + k0, (av1 && k0 + cA < K) ? 16 : 0);
            cp_async16(sB0[bf], bptr0 + (size_t)k0 * N, (k0 + rB < K) ? 16 : 0);
            cp_async16(sB1[bf], bptr1 + (size_t)k0 * N, (k0 + rB + 8 < K) ? 16 : 0);
            cp_commit();
            cp_wait1();
        } else {
            cp_wait0();
        }
        __syncthreads();

        int buf = it & 1;
        #pragma unroll
        for (int ks = 0; ks < 16; ks += 8) {
            uint32_t ah[2][4], al[2][4];
            #pragma unroll
            for (int mt = 0; mt < 2; mt++) {
                int mr = wm*32 + mt*16 + gid;
                split_tf32(As[buf][mr    ][ks + tig    ], ah[mt][0], al[mt][0]);
                split_tf32(As[buf][mr + 8][ks + tig    ], ah[mt][1], al[mt][1]);
                split_tf32(As[buf][mr    ][ks + tig + 4], ah[mt][2], al[mt][2]);
                split_tf32(As[buf][mr + 8][ks + tig + 4], ah[mt][3], al[mt][3]);
            }
            uint32_t bh[8][2], bl[8][2];
            #pragma unroll
            for (int nt = 0; nt < 8; nt++) {
                int nc = wn*64 + nt*8 + gid;
                split_tf32(Bs[buf][ks + tig    ][nc], bh[nt][0], bl[nt][0]);
                split_tf32(Bs[buf][ks + tig + 4][nc], bh[nt][1], bl[nt][1]);
            }
            // small terms first, then the dominant hi*hi
            #pragma unroll
            for (int mt = 0; mt < 2; mt++)
                #pragma unroll
                for (int nt = 0; nt < 8; nt++)
                    mma_tf32(cacc[mt][nt], al[mt], bh[nt]);
            #pragma unroll
            for (int mt = 0; mt < 2; mt++)
                #pragma unroll
                for (int nt = 0; nt < 8; nt++)
                    mma_tf32(cacc[mt][nt], ah[mt], bl[nt]);
            #pragma unroll
            for (int mt = 0; mt < 2; mt++)
                #pragma unroll
                for (int nt = 0; nt < 8; nt++)
                    mma_tf32(cacc[mt][nt], ah[mt], bh[nt]);
        }
        __syncthreads();
    }

    // ---- epilogue ----
    #pragma unroll
    for (int mt = 0; mt < 2; mt++) {
        #pragma unroll
        for (int half = 0; half < 2; half++) {
            int r  = wm*32 + mt*16 + gid + half*8;
            int gm = m_base + r;
            float gate = 1.f;
            if (mode == GM_MOE_DOWN) gate = g_assign_gate[gm];
            #pragma unroll
            for (int nt = 0; nt < 8; nt++) {
                int c = n_base + wn*64 + nt*8 + tig*2;
                float v0 = cacc[mt][nt][half*2 + 0] + bias[c];
                float v1 = cacc[mt][nt][half*2 + 1] + bias[c + 1];
                if (mode == GM_PATCH) {
                    v0 += extra[(size_t)(gm & 255)*N + c];
                    v1 += extra[(size_t)(gm & 255)*N + c + 1];
                } else if (mode == GM_RES) {
                    v0 += extra[(size_t)gm*N + c];
                    v1 += extra[(size_t)gm*N + c + 1];
                } else if (mode == GM_MOE_UP) {
                    v0 = 0.5f*v0*(1.f + erff(v0*0.70710678118654752f));
                    v1 = 0.5f*v1*(1.f + erff(v1*0.70710678118654752f));
                } else if (mode == GM_MOE_DOWN) {
                    v0 *= gate; v1 *= gate;
                }
                *(float2*)&Cout[(size_t)gm*N + c] = make_float2(v0, v1);
            }
        }
    }
}

// ---------------- attention ----------------
__global__ void __launch_bounds__(256)
scores_kernel() {
    int bh = blockIdx.z;
    int b = bh >> 3, h = bh & 7;
    const float* Q = g_q  + (size_t)(b*SEQ)*DIM + h*HD;
    const float* K = g_kk + (size_t)(b*SEQ)*DIM + h*HD;
    __shared__ float Qs[64][65], Ks[64][65];
    int tid = threadIdx.x;
    int i0 = blockIdx.x * 64, j0 = blockIdx.y * 64;
    for (int idx = tid; idx < 64*64; idx += 256) {
        int r = idx >> 6, c = idx & 63;
        Qs[r][c] = Q[(size_t)(i0+r)*DIM + c];
        Ks[r][c] = K[(size_t)(j0+r)*DIM + c];
    }
    __syncthreads();
    int ty = tid >> 4, tx = tid & 15;
    float acc[4][4] = {};
    #pragma unroll 8
    for (int kx = 0; kx < 64; kx++) {
        float a[4], bb[4];
        #pragma unroll
        for (int i = 0; i < 4; i++) a[i]  = Qs[ty*4+i][kx];
        #pragma unroll
        for (int j = 0; j < 4; j++) bb[j] = Ks[tx*4+j][kx];
        #pragma unroll
        for (int i = 0; i < 4; i++)
            #pragma unroll
            for (int j = 0; j < 4; j++)
                acc[i][j] += a[i]*bb[j];
    }
    float* Cp = g_attn + (size_t)bh*SEQ*SEQ;
    #pragma unroll
    for (int i = 0; i < 4; i++)
        #pragma unroll
        for (int j = 0; j < 4; j++)
            Cp[(size_t)(i0+ty*4+i)*SEQ + (j0+tx*4+j)] = acc[i][j] * 0.125f;
}

__global__ void softmax256_kernel() {
    float* row = g_attn + (size_t)blockIdx.x * 256;
    int t = threadIdx.x;
    float v = row[t];
    __shared__ float red[256];
    red[t] = v; __syncthreads();
    for (int s = 128; s; s >>= 1) { if (t < s) red[t] = fmaxf(red[t], red[t+s]); __syncthreads(); }
    float mx = red[0]; __syncthreads();
    float e = expf(v - mx);
    red[t] = e; __syncthreads();
    for (int s = 128; s; s >>= 1) { if (t < s) red[t] += red[t+s]; __syncthreads(); }
    row[t] = e / red[0];
}

__global__ void attn_mean_sm_kernel(float* __restrict__ out) {
    int bs = blockIdx.x;        // b*256 + s
    int b = bs >> 8, srow = bs & 255;
    int j = threadIdx.x;
    float v = 0.f;
    #pragma unroll
    for (int h = 0; h < NHEAD; h++)
        v += g_attn[((size_t)(b*NHEAD + h)*SEQ + srow)*SEQ + j];
    v *= (1.f / NHEAD);
    __shared__ float red[256];
    red[j] = v; __syncthreads();
    for (int s = 128; s; s >>= 1) { if (j < s) red[j] = fmaxf(red[j], red[j+s]); __syncthreads(); }
    float mx = red[0]; __syncthreads();
    float e = expf(v - mx);
    red[j] = e; __syncthreads();
    for (int s = 128; s; s >>= 1) { if (j < s) red[j] += red[j+s]; __syncthreads(); }
    out[(size_t)bs*256 + j] = e / red[0];
}

__global__ void __launch_bounds__(256)
attnv_kernel() {
    int bh = blockIdx.z;
    int b = bh >> 3, h = bh & 7;
    const float* Ap = g_attn + (size_t)bh*SEQ*SEQ;
    const float* V  = g_v + (size_t)(b*SEQ)*DIM + h*HD;
    int i0 = blockIdx.x * 64;
    __shared__ float As[64][65], Vs[64][65];
    int tid = threadIdx.x;
    int ty = tid >> 4, tx = tid & 15;
    float acc[4][4] = {};
    for (int c0 = 0; c0 < SEQ; c0 += 64) {
        for (int idx = tid; idx < 64*64; idx += 256) {
            int r = idx >> 6, c = idx & 63;
            As[r][c] = Ap[(size_t)(i0+r)*SEQ + c0 + c];
            Vs[r][c] = V[(size_t)(c0+r)*DIM + c];
        }
        __syncthreads();
        #pragma unroll 8
        for (int kx = 0; kx < 64; kx++) {
            float a[4], bb[4];
            #pragma unroll
            for (int i = 0; i < 4; i++) a[i]  = As[ty*4+i][kx];
            #pragma unroll
            for (int j = 0; j < 4; j++) bb[j] = Vs[kx][tx*4+j];
            #pragma unroll
            for (int i = 0; i < 4; i++)
                #pragma unroll
                for (int j = 0; j < 4; j++)
                    acc[i][j] += a[i]*bb[j];
        }
        __syncthreads();
    }
    #pragma unroll
    for (int i = 0; i < 4; i++)
        #pragma unroll
        for (int j = 0; j < 4; j++)
            g_attout[(size_t)(b*SEQ + i0 + ty*4 + i)*DIM + h*HD + tx*4 + j] = acc[i][j];
}

// ---------------- MoE routing ----------------
__global__ void moe_reset_kernel() {
    int idx = blockIdx.x * 256 + threadIdx.x;
    if (idx < ACAP) g_assign_token[idx] = -1;
    if (idx < NEXP) { g_counts[idx] = 0; g_fill[idx] = 0; g_probsum[idx] = 0.f; }
}

__global__ void router_kernel(const float* __restrict__ x, const float* __restrict__ rw,
                              const float* __restrict__ rb) {
    __shared__ float s_ps[NEXP];
    __shared__ int   s_cnt[NEXP];
    int t = threadIdx.x;
    if (t < NEXP) { s_ps[t] = 0.f; s_cnt[t] = 0; }
    __syncthreads();
    int warp = t >> 5, lane = t & 31;
    int token = blockIdx.x * 8 + warp;
    float acc[NEXP] = {};
    const float* xr = x + (size_t)token * DIM;
    for (int kx = lane; kx < DIM; kx += 32) {
        float xv = xr[kx];
        const float* rr = rw + (size_t)kx * NEXP;
        #pragma unroll
        for (int e = 0; e < NEXP; e++) acc[e] += xv * rr[e];
    }
    #pragma unroll
    for (int e = 0; e < NEXP; e++)
        #pragma unroll
        for (int o = 16; o; o >>= 1)
            acc[e] += __shfl_down_sync(0xffffffffu, acc[e], o);
    if (lane == 0) {
        float p[NEXP], mx = -1e30f;
        #pragma unroll
        for (int e = 0; e < NEXP; e++) { acc[e] += rb[e]; mx = fmaxf(mx, acc[e]); }
        float sum = 0.f;
        #pragma unroll
        for (int e = 0; e < NEXP; e++) { p[e] = expf(acc[e] - mx); sum += p[e]; }
        float inv = 1.f / sum;
        #pragma unroll
        for (int e = 0; e < NEXP; e++) p[e] *= inv;
        int i1 = 0;
        #pragma unroll
        for (int e = 1; e < NEXP; e++) if (p[e] > p[i1]) i1 = e;
        int i2 = (i1 == 0) ? 1 : 0;
        #pragma unroll
        for (int e = 0; e < NEXP; e++) if (e != i1 && p[e] > p[i2]) i2 = e;
        g_topi[token*2]   = i1; g_topv[token*2]   = p[i1];
        g_topi[token*2+1] = i2; g_topv[token*2+1] = p[i2];
        atomicAdd(&s_cnt[i1], 1);
        atomicAdd(&s_cnt[i2], 1);
        #pragma unroll
        for (int e = 0; e < NEXP; e++) atomicAdd(&s_ps[e], p[e]);
    }
    __syncthreads();
    if (t < NEXP) {
        atomicAdd(&g_counts[t], s_cnt[t]);
        atomicAdd(&g_probsum[t], s_ps[t]);
    }
}

__global__ void loss_accum_kernel() {
    float L = 0.f;
    for (int e = 0; e < NEXP; e++)
        L += ((float)g_counts[e] / (float)TOK) * (g_probsum[e] / (float)TOK);
    g_loss[0] += (float)NEXP * L;
}

__global__ void bucket_prep_kernel() {
    if (threadIdx.x == 0) {
        int off = 0;
        for (int e = 0; e < NEXP; e++) {
            g_off[e] = off;
            off += ((g_counts[e] + 127) >> 7) << 7;
        }
        g_off[NEXP] = off;
    }
    __syncthreads();
    for (int tix = threadIdx.x; tix < MAXT; tix += blockDim.x) {
        int e = -1;
        for (int q = 0; q < NEXP; q++)
            if (tix*128 >= g_off[q] && tix*128 < g_off[q+1]) e = q;
        g_tile_expert[tix] = e;
    }
}

__global__ void scatter_kernel() {
    int token = blockIdx.x * 256 + threadIdx.x;
    if (token >= TOK) return;
    #pragma unroll
    for (int kk = 0; kk < 2; kk++) {
        int e = g_topi[token*2 + kk];
        int p = atomicAdd(&g_fill[e], 1);
        int slot = g_off[e] + p;
        g_assign_token[slot] = token;
        g_assign_gate[slot]  = g_topv[token*2 + kk];
        g_token_slot[token*2 + kk] = slot;
    }
}

__global__ void moe_combine_kernel(float* __restrict__ o) {
    int i = blockIdx.x * 256 + threadIdx.x;     // < TOK*DIM
    int token = i >> 9, d = i & 511;
    int s0 = g_token_slot[token*2], s1 = g_token_slot[token*2 + 1];
    o[i] = g_contrib[(size_t)s0*DIM + d] + g_contrib[(size_t)s1*DIM + d];
}

// ---------------- head ----------------
__global__ void fv_kernel(const float* __restrict__ o2, float* __restrict__ out_fv) {
    int b = blockIdx.x, d = threadIdx.x;    // 512 threads
    float s = 0.f;
    for (int t = 0; t < SEQ; t++)
        s += o2[(size_t)(b*SEQ + t)*DIM + d];
    float v = s * (1.f / SEQ);
    out_fv[b*DIM + d] = v;
    g_fv[b*DIM + d] = v;
}

__global__ void logits_kernel(const float* __restrict__ cw, const float* __restrict__ cb,
                              float* __restrict__ out) {
    __shared__ float xf[DIM];
    int b = blockIdx.x, t = threadIdx.x;    // 512 threads
    xf[t] = g_fv[b*DIM + t];
    __syncthreads();
    float acc = 0.f;
    for (int kx = 0; kx < DIM; kx++)
        acc += xf[kx] * cw[(size_t)kx*DIM + t];
    out[b*DIM + t] = acc + cb[t];
}

__global__ void loss_write_kernel(float* __restrict__ dst) { dst[0] = g_loss[0]; }

// ---------------- host ----------------
static void run_moe(const float* xin, const float* rw, const float* rb,
                    const float* w1, const float* b1,
                    const float* w2, const float* b2,
                    float* p_hidden, float* p_contrib, float* o) {
    moe_reset_kernel<<<(ACAP + 255)/256, 256>>>();
    router_kernel<<<TOK/8, 256>>>(xin, rw, rb);
    loss_accum_kernel<<<1, 1>>>();
    bucket_prep_kernel<<<1, 64>>>();
    scatter_kernel<<<TOK/256, 256>>>();
    gemm_tf32_kernel<<<dim3(HID/128, MAXT), 256>>>(xin, w1, b1, nullptr, p_hidden, HID, DIM, GM_MOE_UP);
    gemm_tf32_kernel<<<dim3(DIM/128, MAXT), 256>>>(p_hidden, w2, b2, nullptr, p_contrib, DIM, HID, GM_MOE_DOWN);
    moe_combine_kernel<<<TOK*DIM/256, 256>>>(o);
}

extern "C" void kernel_launch(void* const* d_in, const int* in_sizes, int n_in,
                              void* d_out, int out_size) {
    const float* x     = (const float*)d_in[0];
    const float* pe_w  = (const float*)d_in[1];
    const float* pe_b  = (const float*)d_in[2];
    const float* pos   = (const float*)d_in[3];
    const float* ln1_g = (const float*)d_in[4];
    const float* ln1_b = (const float*)d_in[5];
    const float* ln2_g = (const float*)d_in[6];
    const float* ln2_b = (const float*)d_in[7];
    const float* ln3_g = (const float*)d_in[8];
    const float* ln3_b = (const float*)d_in[9];
    const float* wq = (const float*)d_in[10];
    const float* bq = (const float*)d_in[11];
    const float* wk = (const float*)d_in[12];
    const float* bk = (const float*)d_in[13];
    const float* wv = (const float*)d_in[14];
    const float* bv = (const float*)d_in[15];
    const float* wo = (const float*)d_in[16];
    const float* bo = (const float*)d_in[17];
    const float* m1_rw = (const float*)d_in[18];
    const float* m1_rb = (const float*)d_in[19];
    const float* m1_w1 = (const float*)d_in[20];
    const float* m1_b1 = (const float*)d_in[21];
    const float* m1_w2 = (const float*)d_in[22];
    const float* m1_b2 = (const float*)d_in[23];
    const float* m2_rw = (const float*)d_in[24];
    const float* m2_rb = (const float*)d_in[25];
    const float* m2_w1 = (const float*)d_in[26];
    const float* m2_b1 = (const float*)d_in[27];
    const float* m2_w2 = (const float*)d_in[28];
    const float* m2_b2 = (const float*)d_in[29];
    const float* cls_w = (const float*)d_in[30];
    const float* cls_b = (const float*)d_in[31];
    float* out = (float*)d_out;

    float *p_patches, *p_e, *p_xln, *p_q, *p_k, *p_v, *p_attout, *p_e2, *p_o1, *p_o2,
          *p_hidden, *p_contrib;
    cudaGetSymbolAddress((void**)&p_patches, g_patches);
    cudaGetSymbolAddress((void**)&p_e,       g_e);
    cudaGetSymbolAddress((void**)&p_xln,     g_xln);
    cudaGetSymbolAddress((void**)&p_q,       g_q);
    cudaGetSymbolAddress((void**)&p_k,       g_kk);
    cudaGetSymbolAddress((void**)&p_v,       g_v);
    cudaGetSymbolAddress((void**)&p_attout,  g_attout);
    cudaGetSymbolAddress((void**)&p_e2,      g_e2);
    cudaGetSymbolAddress((void**)&p_o1,      g_o1);
    cudaGetSymbolAddress((void**)&p_o2,      g_o2);
    cudaGetSymbolAddress((void**)&p_hidden,  g_hidden);
    cudaGetSymbolAddress((void**)&p_contrib, g_contrib);

    zero_loss_kernel<<<1, 1>>>();

    // patch embed:  e = patches @ pe_w + pe_b + pos
    patch_kernel<<<(TOK*PD + 255)/256, 256>>>(x);
    dim3 gD(DIM/128, TOK/128);   // (4,64)
    gemm_tf32_kernel<<<gD, 256>>>(p_patches, pe_w, pe_b, pos, p_e, DIM, PD, GM_PATCH);

    // attention
    ln_kernel<<<TOK, 256>>>(p_e, ln1_g, ln1_b, p_xln);
    gemm_tf32_kernel<<<gD, 256>>>(p_xln, wq, bq, nullptr, p_q, DIM, DIM, GM_BIAS);
    gemm_tf32_kernel<<<gD, 256>>>(p_xln, wk, bk, nullptr, p_k, DIM, DIM, GM_BIAS);
    gemm_tf32_kernel<<<gD, 256>>>(p_xln, wv, bv, nullptr, p_v, DIM, DIM, GM_BIAS);
    scores_kernel<<<dim3(4, 4, BATCH*NHEAD), 256>>>();
    softmax256_kernel<<<BATCH*NHEAD*SEQ, 256>>>();
    attn_mean_sm_kernel<<<TOK, 256>>>(out + OFF_ATTN);
    attnv_kernel<<<dim3(4, 1, BATCH*NHEAD), 256>>>();
    gemm_tf32_kernel<<<gD, 256>>>(p_attout, wo, bo, p_e, p_e2, DIM, DIM, GM_RES);

    // MoE 1
    ln_kernel<<<TOK, 256>>>(p_e2, ln2_g, ln2_b, p_xln);
    run_moe(p_xln, m1_rw, m1_rb, m1_w1, m1_b1, m1_w2, m1_b2, p_hidden, p_contrib, p_o1);

    // MoE 2
    ln_kernel<<<TOK, 256>>>(p_o1, ln3_g, ln3_b, p_xln);
    run_moe(p_xln, m2_rw, m2_rb, m2_w1, m2_b1, m2_w2, m2_b2, p_hidden, p_contrib, p_o2);

    // head
    fv_kernel<<<BATCH, 512>>>(p_o2, out + OFF_FV);
    logits_kernel<<<BATCH, 512>>>(cls_w, cls_b, out);
    loss_write_kernel<<<1, 1>>>(out + OFF_LOSS);

    (void)in_sizes; (void)n_in; (void)out_size;
}

// round 8
// speedup vs baseline: 2.4616x; 1.2737x over previous
#include <cuda_runtime.h>
#include <math.h>
#include <stdint.h>

// ---------------- problem constants ----------------
#define BATCH 32
#define SEQ   256
#define DIM   512
#define PD    588      // 3*14*14
#define TOK   (BATCH*SEQ)   // 8192
#define NHEAD 8
#define HD    64
#define NEXP  8
#define HID   2048
#define ACAP  (TOK*2 + NEXP*128)   // 17408, 128-aligned expert segments
#define MAXT  (ACAP/128)           // 136 row tiles

// output layout: logits[32*512], fv[32*512], loss[1], attn_w[32*256*256]
#define OFF_FV    (BATCH*DIM)
#define OFF_LOSS  (2*BATCH*DIM)
#define OFF_ATTN  (2*BATCH*DIM + 1)

// gemm modes
#define GM_BIAS      0
#define GM_PATCH     1
#define GM_RES       2
#define GM_MOE_UP    3
#define GM_MOE_DOWN  4

// ---------------- scratch ----------------
__device__ float g_patches[(size_t)TOK*PD];
__device__ float g_e[(size_t)TOK*DIM];
__device__ float g_xln[(size_t)TOK*DIM];
__device__ float g_q[(size_t)TOK*DIM];
__device__ float g_kk[(size_t)TOK*DIM];
__device__ float g_v[(size_t)TOK*DIM];
__device__ float g_attn[(size_t)BATCH*NHEAD*SEQ*SEQ];
__device__ float g_attout[(size_t)TOK*DIM];
__device__ float g_e2[(size_t)TOK*DIM];
__device__ float g_o1[(size_t)TOK*DIM];
__device__ float g_o2[(size_t)TOK*DIM];
__device__ float g_hidden[(size_t)ACAP*HID];
__device__ float g_contrib[(size_t)ACAP*DIM];
__device__ int   g_topi[TOK*2];
__device__ float g_topv[TOK*2];
__device__ int   g_counts[NEXP];
__device__ int   g_fill[NEXP];
__device__ int   g_off[NEXP+1];
__device__ int   g_tile_expert[MAXT];
__device__ int   g_assign_token[ACAP];
__device__ float g_assign_gate[ACAP];
__device__ int   g_token_slot[TOK*2];
__device__ float g_probsum[NEXP];
__device__ float g_fv[BATCH*DIM];
__device__ float g_loss[1];

// ---------------- ptx helpers ----------------
__device__ __forceinline__ uint32_t cvt_tf32(float x) {
    uint32_t r; asm("cvt.rna.tf32.f32 %0, %1;" : "=r"(r) : "f"(x)); return r;
}
__device__ __forceinline__ void split_tf32(float x, uint32_t& hi, uint32_t& lo) {
    hi = cvt_tf32(x);
    lo = cvt_tf32(x - __uint_as_float(hi));
}
__device__ __forceinline__ uint32_t smem_u32(const void* p) {
    return (uint32_t)__cvta_generic_to_shared(p);
}
__device__ __forceinline__ void cp_async16(uint32_t dst, const void* src, int bytes) {
    asm volatile("cp.async.cg.shared.global [%0], [%1], 16, %2;\n"
                 :: "r"(dst), "l"(src), "r"(bytes));
}
__device__ __forceinline__ void cp_commit() { asm volatile("cp.async.commit_group;\n"); }
__device__ __forceinline__ void cp_wait1()  { asm volatile("cp.async.wait_group 1;\n"); }
__device__ __forceinline__ void cp_wait0()  { asm volatile("cp.async.wait_group 0;\n"); }

__device__ __forceinline__ void mma_tf32(float* c, const uint32_t* a, const uint32_t* b) {
    asm volatile("mma.sync.aligned.m16n8k8.row.col.f32.tf32.tf32.f32 "
                 "{%0,%1,%2,%3},{%4,%5,%6,%7},{%8,%9},{%0,%1,%2,%3};\n"
                 : "+f"(c[0]), "+f"(c[1]), "+f"(c[2]), "+f"(c[3])
                 : "r"(a[0]), "r"(a[1]), "r"(a[2]), "r"(a[3]), "r"(b[0]), "r"(b[1]));
}

// ---------------- small kernels ----------------
__global__ void zero_loss_kernel() { g_loss[0] = 0.f; }

__global__ void patch_kernel(const float* __restrict__ x) {
    int idx = blockIdx.x * 256 + threadIdx.x;
    if (idx >= TOK * PD) return;
    int token = idx / PD;
    int p = idx - token * PD;
    int b = token >> 8;
    int s = token & 255;
    int hr = s >> 4, wc = s & 15;
    int c  = p % 3;
    int pq = p / 3;          // p1*14+p2
    int p2 = pq % 14, p1 = pq / 14;
    g_patches[idx] = x[(((size_t)(b*3 + c)*224) + hr*14 + p1)*224 + wc*14 + p2];
}

__global__ void ln_kernel(const float* __restrict__ x, const float* __restrict__ g,
                          const float* __restrict__ b, float* __restrict__ y) {
    int row = blockIdx.x;
    const float* xr = x + (size_t)row * DIM;
    int t = threadIdx.x;        // 256 threads, 2 elems each
    float v0 = xr[t], v1 = xr[t + 256];
    __shared__ float s1[256], s2[256];
    s1[t] = v0 + v1;
    s2[t] = v0*v0 + v1*v1;
    __syncthreads();
    for (int s = 128; s; s >>= 1) {
        if (t < s) { s1[t] += s1[t+s]; s2[t] += s2[t+s]; }
        __syncthreads();
    }
    float m   = s1[0] * (1.f/512.f);
    float var = s2[0] * (1.f/512.f) - m*m;
    float r   = rsqrtf(var + 1e-5f);
    y[(size_t)row*DIM + t]       = (v0 - m) * r * g[t]     + b[t];
    y[(size_t)row*DIM + t + 256] = (v1 - m) * r * g[t+256] + b[t+256];
}

// ---------------- tf32 tensor-core GEMM ----------------
// C[M,N] = A[M,K] @ B[K,N] (+ epilogue per mode)
// Block tile 128x128, BK=16, 256 threads = 8 warps (4m x 2n), warp tile 32x64.
// 2-stage cp.async pipeline.
// PASSES=3: hi/lo split, accumulate lo*hi + hi*lo + hi*hi -> ~fp32 accuracy.
// PASSES=1: plain tf32 (for GEMMs feeding only smooth ops downstream).
template<int PASSES>
__global__ void __launch_bounds__(256)
gemm_tf32_kernel(const float* __restrict__ A, const float* __restrict__ Bbase,
                 const float* __restrict__ biasbase, const float* __restrict__ extra,
                 float* __restrict__ Cout, int N, int K, int mode)
{
    int tileY = blockIdx.y;
    const float* B = Bbase;
    const float* bias = biasbase;
    if (mode == GM_MOE_UP || mode == GM_MOE_DOWN) {
        int expert = g_tile_expert[tileY];
        if (expert < 0) return;
        B    = Bbase    + (size_t)expert * K * N;
        bias = biasbase + (size_t)expert * N;
    }

    __shared__ float As[2][128][20];    // [m][k], pad 4 -> conflict-free frags
    __shared__ float Bs[2][16][136];    // [k][n], pad 8 -> conflict-free frags

    int tid = threadIdx.x;
    int m_base = tileY * 128;
    int n_base = blockIdx.x * 128;

    // ---- A source: 2 rows per thread (r and r+64), one float4 column each
    int rA = tid >> 2, cA = (tid & 3) * 4;
    const float* aptr0; const float* aptr1;
    bool av0 = true, av1 = true;
    if (mode == GM_MOE_UP) {
        int t0 = g_assign_token[m_base + rA];
        int t1 = g_assign_token[m_base + rA + 64];
        av0 = (t0 >= 0); av1 = (t1 >= 0);
        aptr0 = A + (size_t)(av0 ? t0 : 0) * K + cA;
        aptr1 = A + (size_t)(av1 ? t1 : 0) * K + cA;
    } else {
        aptr0 = A + (size_t)(m_base + rA) * K + cA;
        aptr1 = A + (size_t)(m_base + rA + 64) * K + cA;
    }
    // ---- B source: 2 rows per thread (rB and rB+8), one float4 each
    int rB = tid >> 5;            // 0..7
    int cB = (tid & 31) * 4;      // 0..124
    const float* bptr0 = B + (size_t)rB * N + n_base + cB;
    const float* bptr1 = B + (size_t)(rB + 8) * N + n_base + cB;

    uint32_t sA0[2], sA1[2], sB0[2], sB1[2];
    #pragma unroll
    for (int bf = 0; bf < 2; bf++) {
        sA0[bf] = smem_u32(&As[bf][rA][cA]);
        sA1[bf] = smem_u32(&As[bf][rA + 64][cA]);
        sB0[bf] = smem_u32(&Bs[bf][rB][cB]);
        sB1[bf] = smem_u32(&Bs[bf][rB + 8][cB]);
    }

    int lane = tid & 31, warp = tid >> 5;
    int wm = warp >> 1, wn = warp & 1;
    int gid = lane >> 2, tig = lane & 3;

    float cacc[2][8][4];
    #pragma unroll
    for (int mt = 0; mt < 2; mt++)
        #pragma unroll
        for (int nt = 0; nt < 8; nt++)
            #pragma unroll
            for (int q = 0; q < 4; q++) cacc[mt][nt][q] = 0.f;

    int KT = (K + 15) / 16;

    // prologue: stage 0
    {
        int k0 = 0, bf = 0;
        cp_async16(sA0[bf], aptr0 + k0, (av0 && k0 + cA < K) ? 16 : 0);
        cp_async16(sA1[bf], aptr1 + k0, (av1 && k0 + cA < K) ? 16 : 0);
        cp_async16(sB0[bf], bptr0 + (size_t)k0 * N, (k0 + rB < K) ? 16 : 0);
        cp_async16(sB1[bf], bptr1 + (size_t)k0 * N, (k0 + rB + 8 < K) ? 16 : 0);
        cp_commit();
    }

    for (int it = 0; it < KT; ++it) {
        if (it + 1 < KT) {
            int k0 = (it + 1) * 16, bf = (it + 1) & 1;
            cp_async16(sA0[bf], aptr0 + k0, (av0 && k0 + cA < K) ? 16 : 0);
            cp_async16(sA1[bf], aptr1 + k0, (av1 && k0 + cA < K) ? 16 : 0);
            cp_async16(sB0[bf], bptr0 + (size_t)k0 * N, (k0 + rB < K) ? 16 : 0);
            cp_async16(sB1[bf], bptr1 + (size_t)k0 * N, (k0 + rB + 8 < K) ? 16 : 0);
            cp_commit();
            cp_wait1();
        } else {
            cp_wait0();
        }
        __syncthreads();

        int buf = it & 1;
        #pragma unroll
        for (int ks = 0; ks < 16; ks += 8) {
            if (PASSES == 3) {
                uint32_t ah[2][4], al[2][4];
                #pragma unroll
                for (int mt = 0; mt < 2; mt++) {
                    int mr = wm*32 + mt*16 + gid;
                    split_tf32(As[buf][mr    ][ks + tig    ], ah[mt][0], al[mt][0]);
                    split_tf32(As[buf][mr + 8][ks + tig    ], ah[mt][1], al[mt][1]);
                    split_tf32(As[buf][mr    ][ks + tig + 4], ah[mt][2], al[mt][2]);
                    split_tf32(As[buf][mr + 8][ks + tig + 4], ah[mt][3], al[mt][3]);
                }
                uint32_t bh[8][2], bl[8][2];
                #pragma unroll
                for (int nt = 0; nt < 8; nt++) {
                    int nc = wn*64 + nt*8 + gid;
                    split_tf32(Bs[buf][ks + tig    ][nc], bh[nt][0], bl[nt][0]);
                    split_tf32(Bs[buf][ks + tig + 4][nc], bh[nt][1], bl[nt][1]);
                }
                // small terms first, then the dominant hi*hi
                #pragma unroll
                for (int mt = 0; mt < 2; mt++)
                    #pragma unroll
                    for (int nt = 0; nt < 8; nt++)
                        mma_tf32(cacc[mt][nt], al[mt], bh[nt]);
                #pragma unroll
                for (int mt = 0; mt < 2; mt++)
                    #pragma unroll
                    for (int nt = 0; nt < 8; nt++)
                        mma_tf32(cacc[mt][nt], ah[mt], bl[nt]);
                #pragma unroll
                for (int mt = 0; mt < 2; mt++)
                    #pragma unroll
                    for (int nt = 0; nt < 8; nt++)
                        mma_tf32(cacc[mt][nt], ah[mt], bh[nt]);
            } else {
                uint32_t ah[2][4];
                #pragma unroll
                for (int mt = 0; mt < 2; mt++) {
                    int mr = wm*32 + mt*16 + gid;
                    ah[mt][0] = cvt_tf32(As[buf][mr    ][ks + tig    ]);
                    ah[mt][1] = cvt_tf32(As[buf][mr + 8][ks + tig    ]);
                    ah[mt][2] = cvt_tf32(As[buf][mr    ][ks + tig + 4]);
                    ah[mt][3] = cvt_tf32(As[buf][mr + 8][ks + tig + 4]);
                }
                uint32_t bh[8][2];
                #pragma unroll
                for (int nt = 0; nt < 8; nt++) {
                    int nc = wn*64 + nt*8 + gid;
                    bh[nt][0] = cvt_tf32(Bs[buf][ks + tig    ][nc]);
                    bh[nt][1] = cvt_tf32(Bs[buf][ks + tig + 4][nc]);
                }
                #pragma unroll
                for (int mt = 0; mt < 2; mt++)
                    #pragma unroll
                    for (int nt = 0; nt < 8; nt++)
                        mma_tf32(cacc[mt][nt], ah[mt], bh[nt]);
            }
        }
        __syncthreads();
    }

    // ---- epilogue ----
    #pragma unroll
    for (int mt = 0; mt < 2; mt++) {
        #pragma unroll
        for (int half = 0; half < 2; half++) {
            int r  = wm*32 + mt*16 + gid + half*8;
            int gm = m_base + r;
            float gate = 1.f;
            if (mode == GM_MOE_DOWN) gate = g_assign_gate[gm];
            #pragma unroll
            for (int nt = 0; nt < 8; nt++) {
                int c = n_base + wn*64 + nt*8 + tig*2;
                float v0 = cacc[mt][nt][half*2 + 0] + bias[c];
                float v1 = cacc[mt][nt][half*2 + 1] + bias[c + 1];
                if (mode == GM_PATCH) {
                    v0 += extra[(size_t)(gm & 255)*N + c];
                    v1 += extra[(size_t)(gm & 255)*N + c + 1];
                } else if (mode == GM_RES) {
                    v0 += extra[(size_t)gm*N + c];
                    v1 += extra[(size_t)gm*N + c + 1];
                } else if (mode == GM_MOE_UP) {
                    v0 = 0.5f*v0*(1.f + erff(v0*0.70710678118654752f));
                    v1 = 0.5f*v1*(1.f + erff(v1*0.70710678118654752f));
                } else if (mode == GM_MOE_DOWN) {
                    v0 *= gate; v1 *= gate;
                }
                *(float2*)&Cout[(size_t)gm*N + c] = make_float2(v0, v1);
            }
        }
    }
}

// ---------------- attention ----------------
__global__ void __launch_bounds__(256)
scores_kernel() {
    int bh = blockIdx.z;
    int b = bh >> 3, h = bh & 7;
    const float* Q = g_q  + (size_t)(b*SEQ)*DIM + h*HD;
    const float* K = g_kk + (size_t)(b*SEQ)*DIM + h*HD;
    __shared__ float Qs[64][65], Ks[64][65];
    int tid = threadIdx.x;
    int i0 = blockIdx.x * 64, j0 = blockIdx.y * 64;
    for (int idx = tid; idx < 64*64; idx += 256) {
        int r = idx >> 6, c = idx & 63;
        Qs[r][c] = Q[(size_t)(i0+r)*DIM + c];
        Ks[r][c] = K[(size_t)(j0+r)*DIM + c];
    }
    __syncthreads();
    int ty = tid >> 4, tx = tid & 15;
    float acc[4][4] = {};
    #pragma unroll 8
    for (int kx = 0; kx < 64; kx++) {
        float a[4], bb[4];
        #pragma unroll
        for (int i = 0; i < 4; i++) a[i]  = Qs[ty*4+i][kx];
        #pragma unroll
        for (int j = 0; j < 4; j++) bb[j] = Ks[tx*4+j][kx];
        #pragma unroll
        for (int i = 0; i < 4; i++)
            #pragma unroll
            for (int j = 0; j < 4; j++)
                acc[i][j] += a[i]*bb[j];
    }
    float* Cp = g_attn + (size_t)bh*SEQ*SEQ;
    #pragma unroll
    for (int i = 0; i < 4; i++)
        #pragma unroll
        for (int j = 0; j < 4; j++)
            Cp[(size_t)(i0+ty*4+i)*SEQ + (j0+tx*4+j)] = acc[i][j] * 0.125f;
}

__global__ void softmax256_kernel() {
    float* row = g_attn + (size_t)blockIdx.x * 256;
    int t = threadIdx.x;
    float v = row[t];
    __shared__ float red[256];
    red[t] = v; __syncthreads();
    for (int s = 128; s; s >>= 1) { if (t < s) red[t] = fmaxf(red[t], red[t+s]); __syncthreads(); }
    float mx = red[0]; __syncthreads();
    float e = expf(v - mx);
    red[t] = e; __syncthreads();
    for (int s = 128; s; s >>= 1) { if (t < s) red[t] += red[t+s]; __syncthreads(); }
    row[t] = e / red[0];
}

__global__ void attn_mean_sm_kernel(float* __restrict__ out) {
    int bs = blockIdx.x;        // b*256 + s
    int b = bs >> 8, srow = bs & 255;
    int j = threadIdx.x;
    float v = 0.f;
    #pragma unroll
    for (int h = 0; h < NHEAD; h++)
        v += g_attn[((size_t)(b*NHEAD + h)*SEQ + srow)*SEQ + j];
    v *= (1.f / NHEAD);
    __shared__ float red[256];
    red[j] = v; __syncthreads();
    for (int s = 128; s; s >>= 1) { if (j < s) red[j] = fmaxf(red[j], red[j+s]); __syncthreads(); }
    float mx = red[0]; __syncthreads();
    float e = expf(v - mx);
    red[j] = e; __syncthreads();
    for (int s = 128; s; s >>= 1) { if (j < s) red[j] += red[j+s]; __syncthreads(); }
    out[(size_t)bs*256 + j] = e / red[0];
}

__global__ void __launch_bounds__(256)
attnv_kernel() {
    int bh = blockIdx.z;
    int b = bh >> 3, h = bh & 7;
    const float* Ap = g_attn + (size_t)bh*SEQ*SEQ;
    const float* V  = g_v + (size_t)(b*SEQ)*DIM + h*HD;
    int i0 = blockIdx.x * 64;
    __shared__ float As[64][65], Vs[64][65];
    int tid = threadIdx.x;
    int ty = tid >> 4, tx = tid & 15;
    float acc[4][4] = {};
    for (int c0 = 0; c0 < SEQ; c0 += 64) {
        for (int idx = tid; idx < 64*64; idx += 256) {
            int r = idx >> 6, c = idx & 63;
            As[r][c] = Ap[(size_t)(i0+r)*SEQ + c0 + c];
            Vs[r][c] = V[(size_t)(c0+r)*DIM + c];
        }
        __syncthreads();
        #pragma unroll 8
        for (int kx = 0; kx < 64; kx++) {
            float a[4], bb[4];
            #pragma unroll
            for (int i = 0; i < 4; i++) a[i]  = As[ty*4+i][kx];
            #pragma unroll
            for (int j = 0; j < 4; j++) bb[j] = Vs[kx][tx*4+j];
            #pragma unroll
            for (int i = 0; i < 4; i++)
                #pragma unroll
                for (int j = 0; j < 4; j++)
                    acc[i][j] += a[i]*bb[j];
        }
        __syncthreads();
    }
    #pragma unroll
    for (int i = 0; i < 4; i++)
        #pragma unroll
        for (int j = 0; j < 4; j++)
            g_attout[(size_t)(b*SEQ + i0 + ty*4 + i)*DIM + h*HD + tx*4 + j] = acc[i][j];
}

// ---------------- MoE routing ----------------
__global__ void moe_reset_kernel() {
    int idx = blockIdx.x * 256 + threadIdx.x;
    if (idx < ACAP) g_assign_token[idx] = -1;
    if (idx < NEXP) { g_counts[idx] = 0; g_fill[idx] = 0; g_probsum[idx] = 0.f; }
}

__global__ void router_kernel(const float* __restrict__ x, const float* __restrict__ rw,
                              const float* __restrict__ rb) {
    __shared__ float s_ps[NEXP];
    __shared__ int   s_cnt[NEXP];
    int t = threadIdx.x;
    if (t < NEXP) { s_ps[t] = 0.f; s_cnt[t] = 0; }
    __syncthreads();
    int warp = t >> 5, lane = t & 31;
    int token = blockIdx.x * 8 + warp;
    float acc[NEXP] = {};
    const float* xr = x + (size_t)token * DIM;
    for (int kx = lane; kx < DIM; kx += 32) {
        float xv = xr[kx];
        const float* rr = rw + (size_t)kx * NEXP;
        #pragma unroll
        for (int e = 0; e < NEXP; e++) acc[e] += xv * rr[e];
    }
    #pragma unroll
    for (int e = 0; e < NEXP; e++)
        #pragma unroll
        for (int o = 16; o; o >>= 1)
            acc[e] += __shfl_down_sync(0xffffffffu, acc[e], o);
    if (lane == 0) {
        float p[NEXP], mx = -1e30f;
        #pragma unroll
        for (int e = 0; e < NEXP; e++) { acc[e] += rb[e]; mx = fmaxf(mx, acc[e]); }
        float sum = 0.f;
        #pragma unroll
        for (int e = 0; e < NEXP; e++) { p[e] = expf(acc[e] - mx); sum += p[e]; }
        float inv = 1.f / sum;
        #pragma unroll
        for (int e = 0; e < NEXP; e++) p[e] *= inv;
        int i1 = 0;
        #pragma unroll
        for (int e = 1; e < NEXP; e++) if (p[e] > p[i1]) i1 = e;
        int i2 = (i1 == 0) ? 1 : 0;
        #pragma unroll
        for (int e = 0; e < NEXP; e++) if (e != i1 && p[e] > p[i2]) i2 = e;
        g_topi[token*2]   = i1; g_topv[token*2]   = p[i1];
        g_topi[token*2+1] = i2; g_topv[token*2+1] = p[i2];
        atomicAdd(&s_cnt[i1], 1);
        atomicAdd(&s_cnt[i2], 1);
        #pragma unroll
        for (int e = 0; e < NEXP; e++) atomicAdd(&s_ps[e], p[e]);
    }
    __syncthreads();
    if (t < NEXP) {
        atomicAdd(&g_counts[t], s_cnt[t]);
        atomicAdd(&g_probsum[t], s_ps[t]);
    }
}

__global__ void loss_accum_kernel() {
    float L = 0.f;
    for (int e = 0; e < NEXP; e++)
        L += ((float)g_counts[e] / (float)TOK) * (g_probsum[e] / (float)TOK);
    g_loss[0] += (float)NEXP * L;
}

__global__ void bucket_prep_kernel() {
    if (threadIdx.x == 0) {
        int off = 0;
        for (int e = 0; e < NEXP; e++) {
            g_off[e] = off;
            off += ((g_counts[e] + 127) >> 7) << 7;
        }
        g_off[NEXP] = off;
    }
    __syncthreads();
    for (int tix = threadIdx.x; tix < MAXT; tix += blockDim.x) {
        int e = -1;
        for (int q = 0; q < NEXP; q++)
            if (tix*128 >= g_off[q] && tix*128 < g_off[q+1]) e = q;
        g_tile_expert[tix] = e;
    }
}

__global__ void scatter_kernel() {
    int token = blockIdx.x * 256 + threadIdx.x;
    if (token >= TOK) return;
    #pragma unroll
    for (int kk = 0; kk < 2; kk++) {
        int e = g_topi[token*2 + kk];
        int p = atomicAdd(&g_fill[e], 1);
        int slot = g_off[e] + p;
        g_assign_token[slot] = token;
        g_assign_gate[slot]  = g_topv[token*2 + kk];
        g_token_slot[token*2 + kk] = slot;
    }
}

__global__ void moe_combine_kernel(float* __restrict__ o) {
    int i = blockIdx.x * 256 + threadIdx.x;     // < TOK*DIM
    int token = i >> 9, d = i & 511;
    int s0 = g_token_slot[token*2], s1 = g_token_slot[token*2 + 1];
    o[i] = g_contrib[(size_t)s0*DIM + d] + g_contrib[(size_t)s1*DIM + d];
}

// ---------------- head ----------------
__global__ void fv_kernel(const float* __restrict__ o2, float* __restrict__ out_fv) {
    int b = blockIdx.x, d = threadIdx.x;    // 512 threads
    float s = 0.f;
    for (int t = 0; t < SEQ; t++)
        s += o2[(size_t)(b*SEQ + t)*DIM + d];
    float v = s * (1.f / SEQ);
    out_fv[b*DIM + d] = v;
    g_fv[b*DIM + d] = v;
}

__global__ void logits_kernel(const float* __restrict__ cw, const float* __restrict__ cb,
                              float* __restrict__ out) {
    __shared__ float xf[DIM];
    int b = blockIdx.x, t = threadIdx.x;    // 512 threads
    xf[t] = g_fv[b*DIM + t];
    __syncthreads();
    float acc = 0.f;
    for (int kx = 0; kx < DIM; kx++)
        acc += xf[kx] * cw[(size_t)kx*DIM + t];
    out[b*DIM + t] = acc + cb[t];
}

__global__ void loss_write_kernel(float* __restrict__ dst) { dst[0] = g_loss[0]; }

// ---------------- host ----------------
static void run_moe(const float* xin, const float* rw, const float* rb,
                    const float* w1, const float* b1,
                    const float* w2, const float* b2,
                    float* p_hidden, float* p_contrib, float* o, bool precise) {
    moe_reset_kernel<<<(ACAP + 255)/256, 256>>>();
    router_kernel<<<TOK/8, 256>>>(xin, rw, rb);
    loss_accum_kernel<<<1, 1>>>();
    bucket_prep_kernel<<<1, 64>>>();
    scatter_kernel<<<TOK/256, 256>>>();
    if (precise) {
        gemm_tf32_kernel<3><<<dim3(HID/128, MAXT), 256>>>(xin, w1, b1, nullptr, p_hidden, HID, DIM, GM_MOE_UP);
        gemm_tf32_kernel<3><<<dim3(DIM/128, MAXT), 256>>>(p_hidden, w2, b2, nullptr, p_contrib, DIM, HID, GM_MOE_DOWN);
    } else {
        gemm_tf32_kernel<1><<<dim3(HID/128, MAXT), 256>>>(xin, w1, b1, nullptr, p_hidden, HID, DIM, GM_MOE_UP);
        gemm_tf32_kernel<1><<<dim3(DIM/128, MAXT), 256>>>(p_hidden, w2, b2, nullptr, p_contrib, DIM, HID, GM_MOE_DOWN);
    }
    moe_combine_kernel<<<TOK*DIM/256, 256>>>(o);
}

extern "C" void kernel_launch(void* const* d_in, const int* in_sizes, int n_in,
                              void* d_out, int out_size) {
    const float* x     = (const float*)d_in[0];
    const float* pe_w  = (const float*)d_in[1];
    const float* pe_b  = (const float*)d_in[2];
    const float* pos   = (const float*)d_in[3];
    const float* ln1_g = (const float*)d_in[4];
    const float* ln1_b = (const float*)d_in[5];
    const float* ln2_g = (const float*)d_in[6];
    const float* ln2_b = (const float*)d_in[7];
    const float* ln3_g = (const float*)d_in[8];
    const float* ln3_b = (const float*)d_in[9];
    const float* wq = (const float*)d_in[10];
    const float* bq = (const float*)d_in[11];
    const float* wk = (const float*)d_in[12];
    const float* bk = (const float*)d_in[13];
    const float* wv = (const float*)d_in[14];
    const float* bv = (const float*)d_in[15];
    const float* wo = (const float*)d_in[16];
    const float* bo = (const float*)d_in[17];
    const float* m1_rw = (const float*)d_in[18];
    const float* m1_rb = (const float*)d_in[19];
    const float* m1_w1 = (const float*)d_in[20];
    const float* m1_b1 = (const float*)d_in[21];
    const float* m1_w2 = (const float*)d_in[22];
    const float* m1_b2 = (const float*)d_in[23];
    const float* m2_rw = (const float*)d_in[24];
    const float* m2_rb = (const float*)d_in[25];
    const float* m2_w1 = (const float*)d_in[26];
    const float* m2_b1 = (const float*)d_in[27];
    const float* m2_w2 = (const float*)d_in[28];
    const float* m2_b2 = (const float*)d_in[29];
    const float* cls_w = (const float*)d_in[30];
    const float* cls_b = (const float*)d_in[31];
    float* out = (float*)d_out;

    float *p_patches, *p_e, *p_xln, *p_q, *p_k, *p_v, *p_attout, *p_e2, *p_o1, *p_o2,
          *p_hidden, *p_contrib;
    cudaGetSymbolAddress((void**)&p_patches, g_patches);
    cudaGetSymbolAddress((void**)&p_e,       g_e);
    cudaGetSymbolAddress((void**)&p_xln,     g_xln);
    cudaGetSymbolAddress((void**)&p_q,       g_q);
    cudaGetSymbolAddress((void**)&p_k,       g_kk);
    cudaGetSymbolAddress((void**)&p_v,       g_v);
    cudaGetSymbolAddress((void**)&p_attout,  g_attout);
    cudaGetSymbolAddress((void**)&p_e2,      g_e2);
    cudaGetSymbolAddress((void**)&p_o1,      g_o1);
    cudaGetSymbolAddress((void**)&p_o2,      g_o2);
    cudaGetSymbolAddress((void**)&p_hidden,  g_hidden);
    cudaGetSymbolAddress((void**)&p_contrib, g_contrib);

    zero_loss_kernel<<<1, 1>>>();

    // patch embed:  e = patches @ pe_w + pe_b + pos
    patch_kernel<<<(TOK*PD + 255)/256, 256>>>(x);
    dim3 gD(DIM/128, TOK/128);   // (4,64)
    gemm_tf32_kernel<3><<<gD, 256>>>(p_patches, pe_w, pe_b, pos, p_e, DIM, PD, GM_PATCH);

    // attention
    ln_kernel<<<TOK, 256>>>(p_e, ln1_g, ln1_b, p_xln);
    gemm_tf32_kernel<3><<<gD, 256>>>(p_xln, wq, bq, nullptr, p_q, DIM, DIM, GM_BIAS);
    gemm_tf32_kernel<3><<<gD, 256>>>(p_xln, wk, bk, nullptr, p_k, DIM, DIM, GM_BIAS);
    gemm_tf32_kernel<3><<<gD, 256>>>(p_xln, wv, bv, nullptr, p_v, DIM, DIM, GM_BIAS);
    scores_kernel<<<dim3(4, 4, BATCH*NHEAD), 256>>>();
    softmax256_kernel<<<BATCH*NHEAD*SEQ, 256>>>();
    attn_mean_sm_kernel<<<TOK, 256>>>(out + OFF_ATTN);
    attnv_kernel<<<dim3(4, 1, BATCH*NHEAD), 256>>>();
    gemm_tf32_kernel<3><<<gD, 256>>>(p_attout, wo, bo, p_e, p_e2, DIM, DIM, GM_RES);

    // MoE 1 (feeds MoE2's router -> precise)
    ln_kernel<<<TOK, 256>>>(p_e2, ln2_g, ln2_b, p_xln);
    run_moe(p_xln, m1_rw, m1_rb, m1_w1, m1_b1, m1_w2, m1_b2, p_hidden, p_contrib, p_o1, true);

    // MoE 2 (feeds only smooth ops -> fast single-pass tf32)
    ln_kernel<<<TOK, 256>>>(p_o1, ln3_g, ln3_b, p_xln);
    run_moe(p_xln, m2_rw, m2_rb, m2_w1, m2_b1, m2_w2, m2_b2, p_hidden, p_contrib, p_o2, false);

    // head
    fv_kernel<<<BATCH, 512>>>(p_o2, out + OFF_FV);
    logits_kernel<<<BATCH, 512>>>(cls_w, cls_b, out);
    loss_write_kernel<<<1, 1>>>(out + OFF_LOSS);

    (void)in_sizes; (void)n_in; (void)out_size;
}

// round 9
// speedup vs baseline: 3.2508x; 1.3206x over previous
#include <cuda_runtime.h>
#include <cuda_bf16.h>
#include <math.h>
#include <stdint.h>

// ---------------- problem constants ----------------
#define BATCH 32
#define SEQ   256
#define DIM   512
#define PD    588      // 3*14*14
#define TOK   (BATCH*SEQ)   // 8192
#define NHEAD 8
#define HD    64
#define NEXP  8
#define HID   2048
#define ACAP  (TOK*2 + NEXP*128)   // 17408, 128-aligned expert segments
#define MAXT  (ACAP/128)           // 136 row tiles

// output layout: logits[32*512], fv[32*512], loss[1], attn_w[32*256*256]
#define OFF_FV    (BATCH*DIM)
#define OFF_LOSS  (2*BATCH*DIM)
#define OFF_ATTN  (2*BATCH*DIM + 1)

// gemm modes
#define GM_BIAS      0
#define GM_PATCH     1
#define GM_RES       2
#define GM_MOE_UP    3
#define GM_MOE_DOWN  4

// ---------------- scratch ----------------
__device__ float g_patches[(size_t)TOK*PD];
__device__ float g_e[(size_t)TOK*DIM];
__device__ float g_xln[(size_t)TOK*DIM];
__device__ float g_q[(size_t)TOK*DIM];
__device__ float g_kk[(size_t)TOK*DIM];
__device__ float g_v[(size_t)TOK*DIM];
__device__ float g_attn[(size_t)BATCH*NHEAD*SEQ*SEQ];
__device__ float g_attout[(size_t)TOK*DIM];
__device__ float g_e2[(size_t)TOK*DIM];
__device__ float g_o1[(size_t)TOK*DIM];
__device__ float g_o2[(size_t)TOK*DIM];
__device__ float g_hidden[(size_t)ACAP*HID];
__device__ float g_contrib[(size_t)ACAP*DIM];
__device__ int   g_topi[TOK*2];
__device__ float g_topv[TOK*2];
__device__ int   g_counts[NEXP];
__device__ int   g_fill[NEXP];
__device__ int   g_off[NEXP+1];
__device__ int   g_tile_expert[MAXT];
__device__ int   g_assign_token[ACAP];
__device__ float g_assign_gate[ACAP];
__device__ int   g_token_slot[TOK*2];
__device__ float g_probsum[NEXP];
__device__ float g_fv[BATCH*DIM];
__device__ float g_loss[1];

// ---------------- ptx helpers ----------------
__device__ __forceinline__ uint32_t cvt_tf32(float x) {
    uint32_t r; asm("cvt.rna.tf32.f32 %0, %1;" : "=r"(r) : "f"(x)); return r;
}
__device__ __forceinline__ uint32_t smem_u32(const void* p) {
    return (uint32_t)__cvta_generic_to_shared(p);
}
__device__ __forceinline__ void cp_async16(uint32_t dst, const void* src, int bytes) {
    asm volatile("cp.async.cg.shared.global [%0], [%1], 16, %2;\n"
                 :: "r"(dst), "l"(src), "r"(bytes));
}
__device__ __forceinline__ void cp_commit() { asm volatile("cp.async.commit_group;\n"); }
__device__ __forceinline__ void cp_wait1()  { asm volatile("cp.async.wait_group 1;\n"); }
__device__ __forceinline__ void cp_wait0()  { asm volatile("cp.async.wait_group 0;\n"); }

__device__ __forceinline__ void mma_tf32(float* c, const uint32_t* a, const uint32_t* b) {
    asm volatile("mma.sync.aligned.m16n8k8.row.col.f32.tf32.tf32.f32 "
                 "{%0,%1,%2,%3},{%4,%5,%6,%7},{%8,%9},{%0,%1,%2,%3};\n"
                 : "+f"(c[0]), "+f"(c[1]), "+f"(c[2]), "+f"(c[3])
                 : "r"(a[0]), "r"(a[1]), "r"(a[2]), "r"(a[3]), "r"(b[0]), "r"(b[1]));
}
__device__ __forceinline__ void mma_bf16(float* c, const uint32_t* a, const uint32_t* b) {
    asm volatile("mma.sync.aligned.m16n8k16.row.col.f32.bf16.bf16.f32 "
                 "{%0,%1,%2,%3},{%4,%5,%6,%7},{%8,%9},{%0,%1,%2,%3};\n"
                 : "+f"(c[0]), "+f"(c[1]), "+f"(c[2]), "+f"(c[3])
                 : "r"(a[0]), "r"(a[1]), "r"(a[2]), "r"(a[3]), "r"(b[0]), "r"(b[1]));
}

// split pair of fp32 into packed bf16 hi + packed bf16 lo (residual)
__device__ __forceinline__ uint32_t pack_split_bf16(float x0, float x1, uint32_t& lo) {
    __nv_bfloat162 h = __floats2bfloat162_rn(x0, x1);   // .x = x0 (low half)
    float h0 = __low2float(h), h1 = __high2float(h);
    __nv_bfloat162 l = __floats2bfloat162_rn(x0 - h0, x1 - h1);
    lo = *reinterpret_cast<uint32_t*>(&l);
    return *reinterpret_cast<uint32_t*>(&h);
}

// ---------------- small kernels ----------------
__global__ void zero_loss_kernel() { g_loss[0] = 0.f; }

__global__ void patch_kernel(const float* __restrict__ x) {
    int idx = blockIdx.x * 256 + threadIdx.x;
    if (idx >= TOK * PD) return;
    int token = idx / PD;
    int p = idx - token * PD;
    int b = token >> 8;
    int s = token & 255;
    int hr = s >> 4, wc = s & 15;
    int c  = p % 3;
    int pq = p / 3;          // p1*14+p2
    int p2 = pq % 14, p1 = pq / 14;
    g_patches[idx] = x[(((size_t)(b*3 + c)*224) + hr*14 + p1)*224 + wc*14 + p2];
}

__global__ void ln_kernel(const float* __restrict__ x, const float* __restrict__ g,
                          const float* __restrict__ b, float* __restrict__ y) {
    int row = blockIdx.x;
    const float* xr = x + (size_t)row * DIM;
    int t = threadIdx.x;        // 256 threads, 2 elems each
    float v0 = xr[t], v1 = xr[t + 256];
    __shared__ float s1[256], s2[256];
    s1[t] = v0 + v1;
    s2[t] = v0*v0 + v1*v1;
    __syncthreads();
    for (int s = 128; s; s >>= 1) {
        if (t < s) { s1[t] += s1[t+s]; s2[t] += s2[t+s]; }
        __syncthreads();
    }
    float m   = s1[0] * (1.f/512.f);
    float var = s2[0] * (1.f/512.f) - m*m;
    float r   = rsqrtf(var + 1e-5f);
    y[(size_t)row*DIM + t]       = (v0 - m) * r * g[t]     + b[t];
    y[(size_t)row*DIM + t + 256] = (v1 - m) * r * g[t+256] + b[t+256];
}

// ---------------- 3xBF16 tensor-core GEMM (fp32-accurate, precision-critical path) ----
// C[M,N] = A[M,K] @ B[K,N] (+ epilogue per mode)
// Block tile 128x128, BK=16, 256 threads = 8 warps (4m x 2n), warp tile 32x64.
// Each operand split hi/lo bf16 ONCE at smem-store time; mma.m16n8k16 x 3 passes
// (lo*hi + hi*lo + hi*hi). Residual ~2^-17 per product.
// smem layout [k2][row] stride 136 words: conflict-free STS and fragment LDS.
__global__ void __launch_bounds__(256)
gemm_bf16x3_kernel(const float* __restrict__ A, const float* __restrict__ Bbase,
                   const float* __restrict__ biasbase, const float* __restrict__ extra,
                   float* __restrict__ Cout, int N, int K, int mode)
{
    int tileY = blockIdx.y;
    const float* B = Bbase;
    const float* bias = biasbase;
    if (mode == GM_MOE_UP || mode == GM_MOE_DOWN) {
        int expert = g_tile_expert[tileY];
        if (expert < 0) return;
        B    = Bbase    + (size_t)expert * K * N;
        bias = biasbase + (size_t)expert * N;
    }

    __shared__ uint32_t Ah[2][8][136];
    __shared__ uint32_t Al[2][8][136];
    __shared__ uint32_t Bh[2][8][136];
    __shared__ uint32_t Bl[2][8][136];

    int tid = threadIdx.x;
    int m_base = tileY * 128;
    int n_base = blockIdx.x * 128;

    // ---- A source: one row per thread (mA), 8 consecutive k at kA
    int mA = tid & 127;
    int kA = (tid >> 7) * 8;          // 0 or 8
    const float* aptr;
    bool avalid = true;
    if (mode == GM_MOE_UP) {
        int t0 = g_assign_token[m_base + mA];
        avalid = (t0 >= 0);
        aptr = A + (size_t)(avalid ? t0 : 0) * K + kA;
    } else {
        aptr = A + (size_t)(m_base + mA) * K + kA;
    }
    // ---- B source: 4 n (stride 32), 2 adjacent k rows at kB
    int nB = tid & 31;
    int kB = (tid >> 5) * 2;          // 0,2,..,14
    const float* bptr = B + (size_t)kB * N + n_base + nB;

    int lane = tid & 31, warp = tid >> 5;
    int wm = warp >> 1, wn = warp & 1;
    int gid = lane >> 2, tig = lane & 3;

    float cacc[2][8][4];
    #pragma unroll
    for (int mt = 0; mt < 2; mt++)
        #pragma unroll
        for (int nt = 0; nt < 8; nt++)
            #pragma unroll
            for (int q = 0; q < 4; q++) cacc[mt][nt][q] = 0.f;

    int KT = (K + 15) >> 4;
    float ra[8], rb[8];

    // ---- load tile 0 into regs
    {
        #pragma unroll
        for (int u = 0; u < 8; u += 4) {
            int kg = kA + u;
            if (avalid && kg < K) {
                float4 v = *(const float4*)(aptr + u);
                ra[u] = v.x; ra[u+1] = v.y; ra[u+2] = v.z; ra[u+3] = v.w;
            } else { ra[u] = ra[u+1] = ra[u+2] = ra[u+3] = 0.f; }
        }
        #pragma unroll
        for (int j = 0; j < 4; j++)
            #pragma unroll
            for (int i = 0; i < 2; i++) {
                int kg = kB + i;
                rb[j*2+i] = (kg < K) ? bptr[(size_t)i * N + 32*j] : 0.f;
            }
    }
    // ---- split+store stage 0
    {
        #pragma unroll
        for (int p = 0; p < 4; p++) {
            uint32_t lo, hi = pack_split_bf16(ra[2*p], ra[2*p+1], lo);
            Ah[0][(kA>>1)+p][mA] = hi;
            Al[0][(kA>>1)+p][mA] = lo;
        }
        #pragma unroll
        for (int j = 0; j < 4; j++) {
            uint32_t lo, hi = pack_split_bf16(rb[2*j], rb[2*j+1], lo);
            Bh[0][kB>>1][nB + 32*j] = hi;
            Bl[0][kB>>1][nB + 32*j] = lo;
        }
    }
    __syncthreads();

    for (int it = 0; it < KT; ++it) {
        int st = it & 1;
        // prefetch next tile into registers (LDG latency overlaps compute)
        if (it + 1 < KT) {
            int k0 = (it + 1) << 4;
            #pragma unroll
            for (int u = 0; u < 8; u += 4) {
                int kg = k0 + kA + u;
                if (avalid && kg < K) {
                    float4 v = *(const float4*)(aptr + k0 + u);
                    ra[u] = v.x; ra[u+1] = v.y; ra[u+2] = v.z; ra[u+3] = v.w;
                } else { ra[u] = ra[u+1] = ra[u+2] = ra[u+3] = 0.f; }
            }
            #pragma unroll
            for (int j = 0; j < 4; j++)
                #pragma unroll
                for (int i = 0; i < 2; i++) {
                    int kg = k0 + kB + i;
                    rb[j*2+i] = (kg < K) ? bptr[(size_t)(k0 + i) * N + 32*j] : 0.f;
                }
        }

        // ---- compute on stage st
        {
            uint32_t ah[2][4], al[2][4], bh[8][2], bl[8][2];
            #pragma unroll
            for (int mt = 0; mt < 2; mt++) {
                int m0 = wm*32 + mt*16 + gid;
                ah[mt][0] = Ah[st][tig  ][m0];
                ah[mt][1] = Ah[st][tig  ][m0+8];
                ah[mt][2] = Ah[st][tig+4][m0];
                ah[mt][3] = Ah[st][tig+4][m0+8];
                al[mt][0] = Al[st][tig  ][m0];
                al[mt][1] = Al[st][tig  ][m0+8];
                al[mt][2] = Al[st][tig+4][m0];
                al[mt][3] = Al[st][tig+4][m0+8];
            }
            #pragma unroll
            for (int nt = 0; nt < 8; nt++) {
                int n0 = wn*64 + nt*8 + gid;
                bh[nt][0] = Bh[st][tig  ][n0];
                bh[nt][1] = Bh[st][tig+4][n0];
                bl[nt][0] = Bl[st][tig  ][n0];
                bl[nt][1] = Bl[st][tig+4][n0];
            }
            // small terms first, dominant hi*hi last
            #pragma unroll
            for (int mt = 0; mt < 2; mt++)
                #pragma unroll
                for (int nt = 0; nt < 8; nt++)
                    mma_bf16(cacc[mt][nt], al[mt], bh[nt]);
            #pragma unroll
            for (int mt = 0; mt < 2; mt++)
                #pragma unroll
                for (int nt = 0; nt < 8; nt++)
                    mma_bf16(cacc[mt][nt], ah[mt], bl[nt]);
            #pragma unroll
            for (int mt = 0; mt < 2; mt++)
                #pragma unroll
                for (int nt = 0; nt < 8; nt++)
                    mma_bf16(cacc[mt][nt], ah[mt], bh[nt]);
        }

        // ---- split+store next stage
        if (it + 1 < KT) {
            int st2 = st ^ 1;
            #pragma unroll
            for (int p = 0; p < 4; p++) {
                uint32_t lo, hi = pack_split_bf16(ra[2*p], ra[2*p+1], lo);
                Ah[st2][(kA>>1)+p][mA] = hi;
                Al[st2][(kA>>1)+p][mA] = lo;
            }
            #pragma unroll
            for (int j = 0; j < 4; j++) {
                uint32_t lo, hi = pack_split_bf16(rb[2*j], rb[2*j+1], lo);
                Bh[st2][kB>>1][nB + 32*j] = hi;
                Bl[st2][kB>>1][nB + 32*j] = lo;
            }
        }
        __syncthreads();
    }

    // ---- epilogue ----
    #pragma unroll
    for (int mt = 0; mt < 2; mt++) {
        #pragma unroll
        for (int half = 0; half < 2; half++) {
            int r  = wm*32 + mt*16 + gid + half*8;
            int gm = m_base + r;
            float gate = 1.f;
            if (mode == GM_MOE_DOWN) gate = g_assign_gate[gm];
            #pragma unroll
            for (int nt = 0; nt < 8; nt++) {
                int c = n_base + wn*64 + nt*8 + tig*2;
                float v0 = cacc[mt][nt][half*2 + 0] + bias[c];
                float v1 = cacc[mt][nt][half*2 + 1] + bias[c + 1];
                if (mode == GM_PATCH) {
                    v0 += extra[(size_t)(gm & 255)*N + c];
                    v1 += extra[(size_t)(gm & 255)*N + c + 1];
                } else if (mode == GM_RES) {
                    v0 += extra[(size_t)gm*N + c];
                    v1 += extra[(size_t)gm*N + c + 1];
                } else if (mode == GM_MOE_UP) {
                    v0 = 0.5f*v0*(1.f + erff(v0*0.70710678118654752f));
                    v1 = 0.5f*v1*(1.f + erff(v1*0.70710678118654752f));
                } else if (mode == GM_MOE_DOWN) {
                    v0 *= gate; v1 *= gate;
                }
                *(float2*)&Cout[(size_t)gm*N + c] = make_float2(v0, v1);
            }
        }
    }
}

// ---------------- 1-pass tf32 GEMM (smooth-only downstream: MoE2) ----------------
__global__ void __launch_bounds__(256)
gemm_tf32_kernel(const float* __restrict__ A, const float* __restrict__ Bbase,
                 const float* __restrict__ biasbase, const float* __restrict__ extra,
                 float* __restrict__ Cout, int N, int K, int mode)
{
    int tileY = blockIdx.y;
    const float* B = Bbase;
    const float* bias = biasbase;
    if (mode == GM_MOE_UP || mode == GM_MOE_DOWN) {
        int expert = g_tile_expert[tileY];
        if (expert < 0) return;
        B    = Bbase    + (size_t)expert * K * N;
        bias = biasbase + (size_t)expert * N;
    }

    __shared__ float As[2][128][20];    // [m][k], pad 4 -> conflict-free frags
    __shared__ float Bs[2][16][136];    // [k][n], pad 8 -> conflict-free frags

    int tid = threadIdx.x;
    int m_base = tileY * 128;
    int n_base = blockIdx.x * 128;

    int rA = tid >> 2, cA = (tid & 3) * 4;
    const float* aptr0; const float* aptr1;
    bool av0 = true, av1 = true;
    if (mode == GM_MOE_UP) {
        int t0 = g_assign_token[m_base + rA];
        int t1 = g_assign_token[m_base + rA + 64];
        av0 = (t0 >= 0); av1 = (t1 >= 0);
        aptr0 = A + (size_t)(av0 ? t0 : 0) * K + cA;
        aptr1 = A + (size_t)(av1 ? t1 : 0) * K + cA;
    } else {
        aptr0 = A + (size_t)(m_base + rA) * K + cA;
        aptr1 = A + (size_t)(m_base + rA + 64) * K + cA;
    }
    int rB = tid >> 5;
    int cB = (tid & 31) * 4;
    const float* bptr0 = B + (size_t)rB * N + n_base + cB;
    const float* bptr1 = B + (size_t)(rB + 8) * N + n_base + cB;

    uint32_t sA0[2], sA1[2], sB0[2], sB1[2];
    #pragma unroll
    for (int bf = 0; bf < 2; bf++) {
        sA0[bf] = smem_u32(&As[bf][rA][cA]);
        sA1[bf] = smem_u32(&As[bf][rA + 64][cA]);
        sB0[bf] = smem_u32(&Bs[bf][rB][cB]);
        sB1[bf] = smem_u32(&Bs[bf][rB + 8][cB]);
    }

    int lane = tid & 31, warp = tid >> 5;
    int wm = warp >> 1, wn = warp & 1;
    int gid = lane >> 2, tig = lane & 3;

    float cacc[2][8][4];
    #pragma unroll
    for (int mt = 0; mt < 2; mt++)
        #pragma unroll
        for (int nt = 0; nt < 8; nt++)
            #pragma unroll
            for (int q = 0; q < 4; q++) cacc[mt][nt][q] = 0.f;

    int KT = (K + 15) / 16;

    {
        int k0 = 0, bf = 0;
        cp_async16(sA0[bf], aptr0 + k0, (av0 && k0 + cA < K) ? 16 : 0);
        cp_async16(sA1[bf], aptr1 + k0, (av1 && k0 + cA < K) ? 16 : 0);
        cp_async16(sB0[bf], bptr0 + (size_t)k0 * N, (k0 + rB < K) ? 16 : 0);
        cp_async16(sB1[bf], bptr1 + (size_t)k0 * N, (k0 + rB + 8 < K) ? 16 : 0);
        cp_commit();
    }

    for (int it = 0; it < KT; ++it) {
        if (it + 1 < KT) {
            int k0 = (it + 1) * 16, bf = (it + 1) & 1;
            cp_async16(sA0[bf], aptr0 + k0, (av0 && k0 + cA < K) ? 16 : 0);
            cp_async16(sA1[bf], aptr1 + k0, (av1 && k0 + cA < K) ? 16 : 0);
            cp_async16(sB0[bf], bptr0 + (size_t)k0 * N, (k0 + rB < K) ? 16 : 0);
            cp_async16(sB1[bf], bptr1 + (size_t)k0 * N, (k0 + rB + 8 < K) ? 16 : 0);
            cp_commit();
            cp_wait1();
        } else {
            cp_wait0();
        }
        __syncthreads();

        int buf = it & 1;
        #pragma unroll
        for (int ks = 0; ks < 16; ks += 8) {
            uint32_t ah[2][4];
            #pragma unroll
            for (int mt = 0; mt < 2; mt++) {
                int mr = wm*32 + mt*16 + gid;
                ah[mt][0] = cvt_tf32(As[buf][mr    ][ks + tig    ]);
                ah[mt][1] = cvt_tf32(As[buf][mr + 8][ks + tig    ]);
                ah[mt][2] = cvt_tf32(As[buf][mr    ][ks + tig + 4]);
                ah[mt][3] = cvt_tf32(As[buf][mr + 8][ks + tig + 4]);
            }
            uint32_t bh[8][2];
            #pragma unroll
            for (int nt = 0; nt < 8; nt++) {
                int nc = wn*64 + nt*8 + gid;
                bh[nt][0] = cvt_tf32(Bs[buf][ks + tig    ][nc]);
                bh[nt][1] = cvt_tf32(Bs[buf][ks + tig + 4][nc]);
            }
            #pragma unroll
            for (int mt = 0; mt < 2; mt++)
                #pragma unroll
                for (int nt = 0; nt < 8; nt++)
                    mma_tf32(cacc[mt][nt], ah[mt], bh[nt]);
        }
        __syncthreads();
    }

    #pragma unroll
    for (int mt = 0; mt < 2; mt++) {
        #pragma unroll
        for (int half = 0; half < 2; half++) {
            int r  = wm*32 + mt*16 + gid + half*8;
            int gm = m_base + r;
            float gate = 1.f;
            if (mode == GM_MOE_DOWN) gate = g_assign_gate[gm];
            #pragma unroll
            for (int nt = 0; nt < 8; nt++) {
                int c = n_base + wn*64 + nt*8 + tig*2;
                float v0 = cacc[mt][nt][half*2 + 0] + bias[c];
                float v1 = cacc[mt][nt][half*2 + 1] + bias[c + 1];
                if (mode == GM_PATCH) {
                    v0 += extra[(size_t)(gm & 255)*N + c];
                    v1 += extra[(size_t)(gm & 255)*N + c + 1];
                } else if (mode == GM_RES) {
                    v0 += extra[(size_t)gm*N + c];
                    v1 += extra[(size_t)gm*N + c + 1];
                } else if (mode == GM_MOE_UP) {
                    v0 = 0.5f*v0*(1.f + erff(v0*0.70710678118654752f));
                    v1 = 0.5f*v1*(1.f + erff(v1*0.70710678118654752f));
                } else if (mode == GM_MOE_DOWN) {
                    v0 *= gate; v1 *= gate;
                }
                *(float2*)&Cout[(size_t)gm*N + c] = make_float2(v0, v1);
            }
        }
    }
}

// ---------------- attention ----------------
__global__ void __launch_bounds__(256)
scores_kernel() {
    int bh = blockIdx.z;
    int b = bh >> 3, h = bh & 7;
    const float* Q = g_q  + (size_t)(b*SEQ)*DIM + h*HD;
    const float* K = g_kk + (size_t)(b*SEQ)*DIM + h*HD;
    __shared__ float Qs[64][65], Ks[64][65];
    int tid = threadIdx.x;
    int i0 = blockIdx.x * 64, j0 = blockIdx.y * 64;
    for (int idx = tid; idx < 64*64; idx += 256) {
        int r = idx >> 6, c = idx & 63;
        Qs[r][c] = Q[(size_t)(i0+r)*DIM + c];
        Ks[r][c] = K[(size_t)(j0+r)*DIM + c];
    }
    __syncthreads();
    int ty = tid >> 4, tx = tid & 15;
    float acc[4][4] = {};
    #pragma unroll 8
    for (int kx = 0; kx < 64; kx++) {
        float a[4], bb[4];
        #pragma unroll
        for (int i = 0; i < 4; i++) a[i]  = Qs[ty*4+i][kx];
        #pragma unroll
        for (int j = 0; j < 4; j++) bb[j] = Ks[tx*4+j][kx];
        #pragma unroll
        for (int i = 0; i < 4; i++)
            #pragma unroll
            for (int j = 0; j < 4; j++)
                acc[i][j] += a[i]*bb[j];
    }
    float* Cp = g_attn + (size_t)bh*SEQ*SEQ;
    #pragma unroll
    for (int i = 0; i < 4; i++)
        #pragma unroll
        for (int j = 0; j < 4; j++)
            Cp[(size_t)(i0+ty*4+i)*SEQ + (j0+tx*4+j)] = acc[i][j] * 0.125f;
}

__global__ void softmax256_kernel() {
    float* row = g_attn + (size_t)blockIdx.x * 256;
    int t = threadIdx.x;
    float v = row[t];
    __shared__ float red[256];
    red[t] = v; __syncthreads();
    for (int s = 128; s; s >>= 1) { if (t < s) red[t] = fmaxf(red[t], red[t+s]); __syncthreads(); }
    float mx = red[0]; __syncthreads();
    float e = expf(v - mx);
    red[t] = e; __syncthreads();
    for (int s = 128; s; s >>= 1) { if (t < s) red[t] += red[t+s]; __syncthreads(); }
    row[t] = e / red[0];
}

__global__ void attn_mean_sm_kernel(float* __restrict__ out) {
    int bs = blockIdx.x;        // b*256 + s
    int b = bs >> 8, srow = bs & 255;
    int j = threadIdx.x;
    float v = 0.f;
    #pragma unroll
    for (int h = 0; h < NHEAD; h++)
        v += g_attn[((size_t)(b*NHEAD + h)*SEQ + srow)*SEQ + j];
    v *= (1.f / NHEAD);
    __shared__ float red[256];
    red[j] = v; __syncthreads();
    for (int s = 128; s; s >>= 1) { if (j < s) red[j] = fmaxf(red[j], red[j+s]); __syncthreads(); }
    float mx = red[0]; __syncthreads();
    float e = expf(v - mx);
    red[j] = e; __syncthreads();
    for (int s = 128; s; s >>= 1) { if (j < s) red[j] += red[j+s]; __syncthreads(); }
    out[(size_t)bs*256 + j] = e / red[0];
}

__global__ void __launch_bounds__(256)
attnv_kernel() {
    int bh = blockIdx.z;
    int b = bh >> 3, h = bh & 7;
    const float* Ap = g_attn + (size_t)bh*SEQ*SEQ;
    const float* V  = g_v + (size_t)(b*SEQ)*DIM + h*HD;
    int i0 = blockIdx.x * 64;
    __shared__ float As[64][65], Vs[64][65];
    int tid = threadIdx.x;
    int ty = tid >> 4, tx = tid & 15;
    float acc[4][4] = {};
    for (int c0 = 0; c0 < SEQ; c0 += 64) {
        for (int idx = tid; idx < 64*64; idx += 256) {
            int r = idx >> 6, c = idx & 63;
            As[r][c] = Ap[(size_t)(i0+r)*SEQ + c0 + c];
            Vs[r][c] = V[(size_t)(c0+r)*DIM + c];
        }
        __syncthreads();
        #pragma unroll 8
        for (int kx = 0; kx < 64; kx++) {
            float a[4], bb[4];
            #pragma unroll
            for (int i = 0; i < 4; i++) a[i]  = As[ty*4+i][kx];
            #pragma unroll
            for (int j = 0; j < 4; j++) bb[j] = Vs[kx][tx*4+j];
            #pragma unroll
            for (int i = 0; i < 4; i++)
                #pragma unroll
                for (int j = 0; j < 4; j++)
                    acc[i][j] += a[i]*bb[j];
        }
        __syncthreads();
    }
    #pragma unroll
    for (int i = 0; i < 4; i++)
        #pragma unroll
        for (int j = 0; j < 4; j++)
            g_attout[(size_t)(b*SEQ + i0 + ty*4 + i)*DIM + h*HD + tx*4 + j] = acc[i][j];
}

// ---------------- MoE routing ----------------
__global__ void moe_reset_kernel() {
    int idx = blockIdx.x * 256 + threadIdx.x;
    if (idx < ACAP) g_assign_token[idx] = -1;
    if (idx < NEXP) { g_counts[idx] = 0; g_fill[idx] = 0; g_probsum[idx] = 0.f; }
}

__global__ void router_kernel(const float* __restrict__ x, const float* __restrict__ rw,
                              const float* __restrict__ rb) {
    __shared__ float s_ps[NEXP];
    __shared__ int   s_cnt[NEXP];
    int t = threadIdx.x;
    if (t < NEXP) { s_ps[t] = 0.f; s_cnt[t] = 0; }
    __syncthreads();
    int warp = t >> 5, lane = t & 31;
    int token = blockIdx.x * 8 + warp;
    float acc[NEXP] = {};
    const float* xr = x + (size_t)token * DIM;
    for (int kx = lane; kx < DIM; kx += 32) {
        float xv = xr[kx];
        const float* rr = rw + (size_t)kx * NEXP;
        #pragma unroll
        for (int e = 0; e < NEXP; e++) acc[e] += xv * rr[e];
    }
    #pragma unroll
    for (int e = 0; e < NEXP; e++)
        #pragma unroll
        for (int o = 16; o; o >>= 1)
            acc[e] += __shfl_down_sync(0xffffffffu, acc[e], o);
    if (lane == 0) {
        float p[NEXP], mx = -1e30f;
        #pragma unroll
        for (int e = 0; e < NEXP; e++) { acc[e] += rb[e]; mx = fmaxf(mx, acc[e]); }
        float sum = 0.f;
        #pragma unroll
        for (int e = 0; e < NEXP; e++) { p[e] = expf(acc[e] - mx); sum += p[e]; }
        float inv = 1.f / sum;
        #pragma unroll
        for (int e = 0; e < NEXP; e++) p[e] *= inv;
        int i1 = 0;
        #pragma unroll
        for (int e = 1; e < NEXP; e++) if (p[e] > p[i1]) i1 = e;
        int i2 = (i1 == 0) ? 1 : 0;
        #pragma unroll
        for (int e = 0; e < NEXP; e++) if (e != i1 && p[e] > p[i2]) i2 = e;
        g_topi[token*2]   = i1; g_topv[token*2]   = p[i1];
        g_topi[token*2+1] = i2; g_topv[token*2+1] = p[i2];
        atomicAdd(&s_cnt[i1], 1);
        atomicAdd(&s_cnt[i2], 1);
        #pragma unroll
        for (int e = 0; e < NEXP; e++) atomicAdd(&s_ps[e], p[e]);
    }
    __syncthreads();
    if (t < NEXP) {
        atomicAdd(&g_counts[t], s_cnt[t]);
        atomicAdd(&g_probsum[t], s_ps[t]);
    }
}

__global__ void loss_accum_kernel() {
    float L = 0.f;
    for (int e = 0; e < NEXP; e++)
        L += ((float)g_counts[e] / (float)TOK) * (g_probsum[e] / (float)TOK);
    g_loss[0] += (float)NEXP * L;
}

__global__ void bucket_prep_kernel() {
    if (threadIdx.x == 0) {
        int off = 0;
        for (int e = 0; e < NEXP; e++) {
            g_off[e] = off;
            off += ((g_counts[e] + 127) >> 7) << 7;
        }
        g_off[NEXP] = off;
    }
    __syncthreads();
    for (int tix = threadIdx.x; tix < MAXT; tix += blockDim.x) {
        int e = -1;
        for (int q = 0; q < NEXP; q++)
            if (tix*128 >= g_off[q] && tix*128 < g_off[q+1]) e = q;
        g_tile_expert[tix] = e;
    }
}

__global__ void scatter_kernel() {
    int token = blockIdx.x * 256 + threadIdx.x;
    if (token >= TOK) return;
    #pragma unroll
    for (int kk = 0; kk < 2; kk++) {
        int e = g_topi[token*2 + kk];
        int p = atomicAdd(&g_fill[e], 1);
        int slot = g_off[e] + p;
        g_assign_token[slot] = token;
        g_assign_gate[slot]  = g_topv[token*2 + kk];
        g_token_slot[token*2 + kk] = slot;
    }
}

__global__ void moe_combine_kernel(float* __restrict__ o) {
    int i = blockIdx.x * 256 + threadIdx.x;     // < TOK*DIM
    int token = i >> 9, d = i & 511;
    int s0 = g_token_slot[token*2], s1 = g_token_slot[token*2 + 1];
    o[i] = g_contrib[(size_t)s0*DIM + d] + g_contrib[(size_t)s1*DIM + d];
}

// ---------------- head ----------------
__global__ void fv_kernel(const float* __restrict__ o2, float* __restrict__ out_fv) {
    int b = blockIdx.x, d = threadIdx.x;    // 512 threads
    float s = 0.f;
    for (int t = 0; t < SEQ; t++)
        s += o2[(size_t)(b*SEQ + t)*DIM + d];
    float v = s * (1.f / SEQ);
    out_fv[b*DIM + d] = v;
    g_fv[b*DIM + d] = v;
}

__global__ void logits_kernel(const float* __restrict__ cw, const float* __restrict__ cb,
                              float* __restrict__ out) {
    __shared__ float xf[DIM];
    int b = blockIdx.x, t = threadIdx.x;    // 512 threads
    xf[t] = g_fv[b*DIM + t];
    __syncthreads();
    float acc = 0.f;
    for (int kx = 0; kx < DIM; kx++)
        acc += xf[kx] * cw[(size_t)kx*DIM + t];
    out[b*DIM + t] = acc + cb[t];
}

__global__ void loss_write_kernel(float* __restrict__ dst) { dst[0] = g_loss[0]; }

// ---------------- host ----------------
static void run_moe(const float* xin, const float* rw, const float* rb,
                    const float* w1, const float* b1,
                    const float* w2, const float* b2,
                    float* p_hidden, float* p_contrib, float* o, bool precise) {
    moe_reset_kernel<<<(ACAP + 255)/256, 256>>>();
    router_kernel<<<TOK/8, 256>>>(xin, rw, rb);
    loss_accum_kernel<<<1, 1>>>();
    bucket_prep_kernel<<<1, 64>>>();
    scatter_kernel<<<TOK/256, 256>>>();
    if (precise) {
        gemm_bf16x3_kernel<<<dim3(HID/128, MAXT), 256>>>(xin, w1, b1, nullptr, p_hidden, HID, DIM, GM_MOE_UP);
        gemm_bf16x3_kernel<<<dim3(DIM/128, MAXT), 256>>>(p_hidden, w2, b2, nullptr, p_contrib, DIM, HID, GM_MOE_DOWN);
    } else {
        gemm_tf32_kernel<<<dim3(HID/128, MAXT), 256>>>(xin, w1, b1, nullptr, p_hidden, HID, DIM, GM_MOE_UP);
        gemm_tf32_kernel<<<dim3(DIM/128, MAXT), 256>>>(p_hidden, w2, b2, nullptr, p_contrib, DIM, HID, GM_MOE_DOWN);
    }
    moe_combine_kernel<<<TOK*DIM/256, 256>>>(o);
}

extern "C" void kernel_launch(void* const* d_in, const int* in_sizes, int n_in,
                              void* d_out, int out_size) {
    const float* x     = (const float*)d_in[0];
    const float* pe_w  = (const float*)d_in[1];
    const float* pe_b  = (const float*)d_in[2];
    const float* pos   = (const float*)d_in[3];
    const float* ln1_g = (const float*)d_in[4];
    const float* ln1_b = (const float*)d_in[5];
    const float* ln2_g = (const float*)d_in[6];
    const float* ln2_b = (const float*)d_in[7];
    const float* ln3_g = (const float*)d_in[8];
    const float* ln3_b = (const float*)d_in[9];
    const float* wq = (const float*)d_in[10];
    const float* bq = (const float*)d_in[11];
    const float* wk = (const float*)d_in[12];
    const float* bk = (const float*)d_in[13];
    const float* wv = (const float*)d_in[14];
    const float* bv = (const float*)d_in[15];
    const float* wo = (const float*)d_in[16];
    const float* bo = (const float*)d_in[17];
    const float* m1_rw = (const float*)d_in[18];
    const float* m1_rb = (const float*)d_in[19];
    const float* m1_w1 = (const float*)d_in[20];
    const float* m1_b1 = (const float*)d_in[21];
    const float* m1_w2 = (const float*)d_in[22];
    const float* m1_b2 = (const float*)d_in[23];
    const float* m2_rw = (const float*)d_in[24];
    const float* m2_rb = (const float*)d_in[25];
    const float* m2_w1 = (const float*)d_in[26];
    const float* m2_b1 = (const float*)d_in[27];
    const float* m2_w2 = (const float*)d_in[28];
    const float* m2_b2 = (const float*)d_in[29];
    const float* cls_w = (const float*)d_in[30];
    const float* cls_b = (const float*)d_in[31];
    float* out = (float*)d_out;

    float *p_patches, *p_e, *p_xln, *p_q, *p_k, *p_v, *p_attout, *p_e2, *p_o1, *p_o2,
          *p_hidden, *p_contrib;
    cudaGetSymbolAddress((void**)&p_patches, g_patches);
    cudaGetSymbolAddress((void**)&p_e,       g_e);
    cudaGetSymbolAddress((void**)&p_xln,     g_xln);
    cudaGetSymbolAddress((void**)&p_q,       g_q);
    cudaGetSymbolAddress((void**)&p_k,       g_kk);
    cudaGetSymbolAddress((void**)&p_v,       g_v);
    cudaGetSymbolAddress((void**)&p_attout,  g_attout);
    cudaGetSymbolAddress((void**)&p_e2,      g_e2);
    cudaGetSymbolAddress((void**)&p_o1,      g_o1);
    cudaGetSymbolAddress((void**)&p_o2,      g_o2);
    cudaGetSymbolAddress((void**)&p_hidden,  g_hidden);
    cudaGetSymbolAddress((void**)&p_contrib, g_contrib);

    zero_loss_kernel<<<1, 1>>>();

    // patch embed:  e = patches @ pe_w + pe_b + pos
    patch_kernel<<<(TOK*PD + 255)/256, 256>>>(x);
    dim3 gD(DIM/128, TOK/128);   // (4,64)
    gemm_bf16x3_kernel<<<gD, 256>>>(p_patches, pe_w, pe_b, pos, p_e, DIM, PD, GM_PATCH);

    // attention
    ln_kernel<<<TOK, 256>>>(p_e, ln1_g, ln1_b, p_xln);
    gemm_bf16x3_kernel<<<gD, 256>>>(p_xln, wq, bq, nullptr, p_q, DIM, DIM, GM_BIAS);
    gemm_bf16x3_kernel<<<gD, 256>>>(p_xln, wk, bk, nullptr, p_k, DIM, DIM, GM_BIAS);
    gemm_bf16x3_kernel<<<gD, 256>>>(p_xln, wv, bv, nullptr, p_v, DIM, DIM, GM_BIAS);
    scores_kernel<<<dim3(4, 4, BATCH*NHEAD), 256>>>();
    softmax256_kernel<<<BATCH*NHEAD*SEQ, 256>>>();
    attn_mean_sm_kernel<<<TOK, 256>>>(out + OFF_ATTN);
    attnv_kernel<<<dim3(4, 1, BATCH*NHEAD), 256>>>();
    gemm_bf16x3_kernel<<<gD, 256>>>(p_attout, wo, bo, p_e, p_e2, DIM, DIM, GM_RES);

    // MoE 1 (feeds MoE2's router -> precise bf16x3)
    ln_kernel<<<TOK, 256>>>(p_e2, ln2_g, ln2_b, p_xln);
    run_moe(p_xln, m1_rw, m1_rb, m1_w1, m1_b1, m1_w2, m1_b2, p_hidden, p_contrib, p_o1, true);

    // MoE 2 (feeds only smooth ops -> fast single-pass tf32)
    ln_kernel<<<TOK, 256>>>(p_o1, ln3_g, ln3_b, p_xln);
    run_moe(p_xln, m2_rw, m2_rb, m2_w1, m2_b1, m2_w2, m2_b2, p_hidden, p_contrib, p_o2, false);

    // head
    fv_kernel<<<BATCH, 512>>>(p_o2, out + OFF_FV);
    logits_kernel<<<BATCH, 512>>>(cls_w, cls_b, out);
    loss_write_kernel<<<1, 1>>>(out + OFF_LOSS);

    (void)in_sizes; (void)n_in; (void)out_size;
}

// round 15
// speedup vs baseline: 3.2844x; 1.0103x over previous
#include <cuda_runtime.h>
#include <cuda_bf16.h>
#include <math.h>
#include <stdint.h>

// ---------------- problem constants ----------------
#define BATCH 32
#define SEQ   256
#define DIM   512
#define PD    588      // 3*14*14
#define PDP   592      // PD padded to k16 multiple
#define TOK   (BATCH*SEQ)   // 8192
#define NHEAD 8
#define HD    64
#define NEXP  8
#define HID   2048
#define ACAP  (TOK*2 + NEXP*128)   // 17408, 128-aligned expert segments
#define MAXT  (ACAP/128)           // 136 row tiles

// output layout: logits[32*512], fv[32*512], loss[1], attn_w[32*256*256]
#define OFF_FV    (BATCH*DIM)
#define OFF_LOSS  (2*BATCH*DIM)
#define OFF_ATTN  (2*BATCH*DIM + 1)

// gemm modes
#define GM_BIAS      0
#define GM_PATCH     1
#define GM_RES       2
#define GM_MOE_UP    3
#define GM_MOE_DOWN  4

// ---------------- scratch ----------------
__device__ __nv_bfloat16 g_pat_h[(size_t)TOK*PDP];
__device__ __nv_bfloat16 g_pat_l[(size_t)TOK*PDP];
__device__ float g_e[(size_t)TOK*DIM];
__device__ float g_xln[(size_t)TOK*DIM];
__device__ __nv_bfloat16 g_xln_h[(size_t)TOK*DIM];
__device__ __nv_bfloat16 g_xln_l[(size_t)TOK*DIM];
__device__ float g_q[(size_t)TOK*DIM];
__device__ float g_kk[(size_t)TOK*DIM];
__device__ float g_v[(size_t)TOK*DIM];
__device__ float g_attn[(size_t)BATCH*NHEAD*SEQ*SEQ];
__device__ __nv_bfloat16 g_att_h[(size_t)TOK*DIM];
__device__ __nv_bfloat16 g_att_l[(size_t)TOK*DIM];
__device__ float g_e2[(size_t)TOK*DIM];
__device__ float g_o1[(size_t)TOK*DIM];
__device__ float g_o2[(size_t)TOK*DIM];
__device__ float g_hidden[(size_t)ACAP*HID];            // MoE2 (tf32 path)
__device__ __nv_bfloat16 g_hid_h[(size_t)ACAP*HID];     // MoE1 (bf16p path)
__device__ __nv_bfloat16 g_hid_l[(size_t)ACAP*HID];
__device__ float g_contrib[(size_t)ACAP*DIM];
// transposed bf16 hi/lo weight planes [n][k]
__device__ __nv_bfloat16 g_peT_h[(size_t)DIM*PDP];
__device__ __nv_bfloat16 g_peT_l[(size_t)DIM*PDP];
__device__ __nv_bfloat16 g_wqT_h[(size_t)DIM*DIM];
__device__ __nv_bfloat16 g_wqT_l[(size_t)DIM*DIM];
__device__ __nv_bfloat16 g_wkT_h[(size_t)DIM*DIM];
__device__ __nv_bfloat16 g_wkT_l[(size_t)DIM*DIM];
__device__ __nv_bfloat16 g_wvT_h[(size_t)DIM*DIM];
__device__ __nv_bfloat16 g_wvT_l[(size_t)DIM*DIM];
__device__ __nv_bfloat16 g_woT_h[(size_t)DIM*DIM];
__device__ __nv_bfloat16 g_woT_l[(size_t)DIM*DIM];
__device__ __nv_bfloat16 g_m1w1T_h[(size_t)NEXP*HID*DIM];
__device__ __nv_bfloat16 g_m1w1T_l[(size_t)NEXP*HID*DIM];
__device__ __nv_bfloat16 g_m1w2T_h[(size_t)NEXP*DIM*HID];
__device__ __nv_bfloat16 g_m1w2T_l[(size_t)NEXP*DIM*HID];
__device__ int   g_topi[TOK*2];
__device__ float g_topv[TOK*2];
__device__ int   g_counts[NEXP];
__device__ int   g_fill[NEXP];
__device__ int   g_off[NEXP+1];
__device__ int   g_tile_expert[MAXT];
__device__ int   g_assign_token[ACAP];
__device__ float g_assign_gate[ACAP];
__device__ int   g_token_slot[TOK*2];
__device__ float g_probsum[NEXP];
__device__ float g_fv[BATCH*DIM];
__device__ float g_loss[1];

// ---------------- ptx helpers ----------------
__device__ __forceinline__ uint32_t cvt_tf32(float x) {
    uint32_t r; asm("cvt.rna.tf32.f32 %0, %1;" : "=r"(r) : "f"(x)); return r;
}
__device__ __forceinline__ uint32_t smem_u32(const void* p) {
    return (uint32_t)__cvta_generic_to_shared(p);
}
__device__ __forceinline__ void cp_async16(uint32_t dst, const void* src, int bytes) {
    asm volatile("cp.async.cg.shared.global [%0], [%1], 16, %2;\n"
                 :: "r"(dst), "l"(src), "r"(bytes));
}
__device__ __forceinline__ void cp_commit() { asm volatile("cp.async.commit_group;\n"); }
__device__ __forceinline__ void cp_wait1()  { asm volatile("cp.async.wait_group 1;\n"); }
__device__ __forceinline__ void cp_wait0()  { asm volatile("cp.async.wait_group 0;\n"); }

__device__ __forceinline__ void mma_tf32(float* c, const uint32_t* a, const uint32_t* b) {
    asm volatile("mma.sync.aligned.m16n8k8.row.col.f32.tf32.tf32.f32 "
                 "{%0,%1,%2,%3},{%4,%5,%6,%7},{%8,%9},{%0,%1,%2,%3};\n"
                 : "+f"(c[0]), "+f"(c[1]), "+f"(c[2]), "+f"(c[3])
                 : "r"(a[0]), "r"(a[1]), "r"(a[2]), "r"(a[3]), "r"(b[0]), "r"(b[1]));
}
__device__ __forceinline__ void mma_bf16(float* c, const uint32_t* a, const uint32_t* b) {
    asm volatile("mma.sync.aligned.m16n8k16.row.col.f32.bf16.bf16.f32 "
                 "{%0,%1,%2,%3},{%4,%5,%6,%7},{%8,%9},{%0,%1,%2,%3};\n"
                 : "+f"(c[0]), "+f"(c[1]), "+f"(c[2]), "+f"(c[3])
                 : "r"(a[0]), "r"(a[1]), "r"(a[2]), "r"(a[3]), "r"(b[0]), "r"(b[1]));
}

// ---------------- small kernels ----------------
__global__ void zero_loss_kernel() { g_loss[0] = 0.f; }

__global__ void patch_kernel(const float* __restrict__ x) {
    int idx = blockIdx.x * 256 + threadIdx.x;
    if (idx >= TOK * PDP) return;
    int token = idx / PDP;
    int p = idx - token * PDP;
    float v = 0.f;
    if (p < PD) {
        int b = token >> 8;
        int s = token & 255;
        int hr = s >> 4, wc = s & 15;
        int c  = p % 3;
        int pq = p / 3;
        int p2 = pq % 14, p1 = pq / 14;
        v = x[(((size_t)(b*3 + c)*224) + hr*14 + p1)*224 + wc*14 + p2];
    }
    __nv_bfloat16 h = __float2bfloat16_rn(v);
    g_pat_h[idx] = h;
    g_pat_l[idx] = __float2bfloat16_rn(v - __bfloat162float(h));
}

// ln with optional bf16 hi/lo split outputs
__global__ void ln_kernel(const float* __restrict__ x, const float* __restrict__ g,
                          const float* __restrict__ b, float* __restrict__ y,
                          __nv_bfloat16* __restrict__ yh, __nv_bfloat16* __restrict__ yl) {
    int row = blockIdx.x;
    const float* xr = x + (size_t)row * DIM;
    int t = threadIdx.x;
    float v0 = xr[t], v1 = xr[t + 256];
    __shared__ float s1[256], s2[256];
    s1[t] = v0 + v1;
    s2[t] = v0*v0 + v1*v1;
    __syncthreads();
    for (int s = 128; s; s >>= 1) {
        if (t < s) { s1[t] += s1[t+s]; s2[t] += s2[t+s]; }
        __syncthreads();
    }
    float m   = s1[0] * (1.f/512.f);
    float var = s2[0] * (1.f/512.f) - m*m;
    float r   = rsqrtf(var + 1e-5f);
    float o0 = (v0 - m) * r * g[t]     + b[t];
    float o1 = (v1 - m) * r * g[t+256] + b[t+256];
    y[(size_t)row*DIM + t]       = o0;
    y[(size_t)row*DIM + t + 256] = o1;
    if (yh) {
        __nv_bfloat16 h0 = __float2bfloat16_rn(o0);
        __nv_bfloat16 h1 = __float2bfloat16_rn(o1);
        yh[(size_t)row*DIM + t]       = h0;
        yh[(size_t)row*DIM + t + 256] = h1;
        yl[(size_t)row*DIM + t]       = __float2bfloat16_rn(o0 - __bfloat162float(h0));
        yl[(size_t)row*DIM + t + 256] = __float2bfloat16_rn(o1 - __bfloat162float(h1));
    }
}

// transpose-convert W[e][Kdim][N] fp32 -> Th/Tl[e][N][Kpad] bf16 hi/lo planes
__global__ void wconv_kernel(const float* __restrict__ W, __nv_bfloat16* __restrict__ Th,
                             __nv_bfloat16* __restrict__ Tl, int Kdim, int N, int Kpad) {
    int e = blockIdx.z;
    int nb = blockIdx.x * 32, kb = blockIdx.y * 32;
    __shared__ float t[32][33];
    int tx = threadIdx.x & 31, ty0 = threadIdx.x >> 5;
    const float* Wp = W + (size_t)e * Kdim * N;
    #pragma unroll
    for (int i = 0; i < 32; i += 8) {
        int kk = kb + ty0 + i;
        t[ty0 + i][tx] = (kk < Kdim) ? Wp[(size_t)kk * N + nb + tx] : 0.f;
    }
    __syncthreads();
    __nv_bfloat16* Thp = Th + (size_t)e * N * Kpad;
    __nv_bfloat16* Tlp = Tl + (size_t)e * N * Kpad;
    int kk = kb + tx;
    if (kk < Kpad) {
        #pragma unroll
        for (int i = 0; i < 32; i += 8) {
            int r = ty0 + i;
            float v = t[tx][r];
            __nv_bfloat16 h = __float2bfloat16_rn(v);
            Thp[(size_t)(nb + r) * Kpad + kk] = h;
            Tlp[(size_t)(nb + r) * Kpad + kk] = __float2bfloat16_rn(v - __bfloat162float(h));
        }
    }
}

// ---------------- 3xBF16 mma.sync GEMM on pre-split planes ----------------
// A planes [m][K] bf16 hi/lo, B planes [n][K] bf16 hi/lo (weights pre-transposed).
// Block tile 128x128, BK=16, 256 threads = 8 warps (4m x 2n), warp tile 32x64.
// cp.async double buffer; smem [row][12 words] (16B-aligned, conflict-free frags).
__global__ void __launch_bounds__(256)
gemm_bf16p_kernel(const __nv_bfloat16* __restrict__ AH_g, const __nv_bfloat16* __restrict__ AL_g,
                  const __nv_bfloat16* __restrict__ BH_g, const __nv_bfloat16* __restrict__ BL_g,
                  const float* __restrict__ biasbase, const float* __restrict__ extra,
                  float* __restrict__ outF, __nv_bfloat16* __restrict__ outH,
                  __nv_bfloat16* __restrict__ outL, int N, int K, int mode)
{
    int tileY = blockIdx.y;
    const __nv_bfloat16 *BH = BH_g, *BL = BL_g;
    const float* bias = biasbase;
    int m_base = tileY * 128;
    if (mode == GM_MOE_UP || mode == GM_MOE_DOWN) {
        int expert = g_tile_expert[tileY];
        if (expert < 0) return;
        BH = BH_g + (size_t)expert * N * K;
        BL = BL_g + (size_t)expert * N * K;
        bias = biasbase + (size_t)expert * N;
    }
    int n_base = blockIdx.x * 128;

    __shared__ __align__(16) uint32_t AHs[2][128*12];
    __shared__ __align__(16) uint32_t ALs[2][128*12];
    __shared__ __align__(16) uint32_t BHs[2][128*12];
    __shared__ __align__(16) uint32_t BLs[2][128*12];

    int tid = threadIdx.x;
    int lrow = tid >> 1, lch = tid & 1;     // loader: row 0..127, 16B chunk 0/1

    const __nv_bfloat16 *ah_src, *al_src;
    bool avalid = true;
    if (mode == GM_MOE_UP) {
        int tok = g_assign_token[m_base + lrow];
        avalid = (tok >= 0);
        ah_src = AH_g + (size_t)(avalid ? tok : 0) * K;
        al_src = AL_g + (size_t)(avalid ? tok : 0) * K;
    } else {
        ah_src = AH_g + (size_t)(m_base + lrow) * K;
        al_src = AL_g + (size_t)(m_base + lrow) * K;
    }
    const __nv_bfloat16* bh_src = BH + (size_t)(n_base + lrow) * K;
    const __nv_bfloat16* bl_src = BL + (size_t)(n_base + lrow) * K;
    int abytes = avalid ? 16 : 0;
    int koff = lch * 8;                     // element offset of this 16B chunk

    uint32_t dAH[2], dAL[2], dBH[2], dBL[2];
    {
        int w = lrow * 12 + lch * 4;
        #pragma unroll
        for (int s = 0; s < 2; s++) {
            dAH[s] = smem_u32(&AHs[s][w]);
            dAL[s] = smem_u32(&ALs[s][w]);
            dBH[s] = smem_u32(&BHs[s][w]);
            dBL[s] = smem_u32(&BLs[s][w]);
        }
    }

    int lane = tid & 31, warp = tid >> 5;
    int wm = warp >> 1, wn = warp & 1;
    int gid = lane >> 2, tig = lane & 3;

    float cacc[2][8][4];
    #pragma unroll
    for (int mt = 0; mt < 2; mt++)
        #pragma unroll
        for (int nt = 0; nt < 8; nt++)
            #pragma unroll
            for (int q = 0; q < 4; q++) cacc[mt][nt][q] = 0.f;

    int KT = K >> 4;

    // prologue: stage 0
    cp_async16(dAH[0], ah_src + koff, abytes);
    cp_async16(dAL[0], al_src + koff, abytes);
    cp_async16(dBH[0], bh_src + koff, 16);
    cp_async16(dBL[0], bl_src + koff, 16);
    cp_commit();

    for (int it = 0; it < KT; ++it) {
        if (it + 1 < KT) {
            int st2 = (it + 1) & 1;
            int k0 = (it + 1) << 4;
            cp_async16(dAH[st2], ah_src + k0 + koff, abytes);
            cp_async16(dAL[st2], al_src + k0 + koff, abytes);
            cp_async16(dBH[st2], bh_src + k0 + koff, 16);
            cp_async16(dBL[st2], bl_src + k0 + koff, 16);
            cp_commit();
            cp_wait1();
        } else {
            cp_wait0();
        }
        __syncthreads();

        int st = it & 1;
        uint32_t ah[2][4], al[2][4], bh[8][2], bl[8][2];
        #pragma unroll
        for (int mt = 0; mt < 2; mt++) {
            int m0 = wm*32 + mt*16 + gid;
            ah[mt][0] = AHs[st][(m0    )*12 + tig    ];
            ah[mt][1] = AHs[st][(m0 + 8)*12 + tig    ];
            ah[mt][2] = AHs[st][(m0    )*12 + tig + 4];
            ah[mt][3] = AHs[st][(m0 + 8)*12 + tig + 4];
            al[mt][0] = ALs[st][(m0    )*12 + tig    ];
            al[mt][1] = ALs[st][(m0 + 8)*12 + tig    ];
            al[mt][2] = ALs[st][(m0    )*12 + tig + 4];
            al[mt][3] = ALs[st][(m0 + 8)*12 + tig + 4];
        }
        #pragma unroll
        for (int nt = 0; nt < 8; nt++) {
            int n0 = wn*64 + nt*8 + gid;
            bh[nt][0] = BHs[st][n0*12 + tig    ];
            bh[nt][1] = BHs[st][n0*12 + tig + 4];
            bl[nt][0] = BLs[st][n0*12 + tig    ];
            bl[nt][1] = BLs[st][n0*12 + tig + 4];
        }
        // small terms first, dominant hi*hi last
        #pragma unroll
        for (int mt = 0; mt < 2; mt++)
            #pragma unroll
            for (int nt = 0; nt < 8; nt++)
                mma_bf16(cacc[mt][nt], al[mt], bh[nt]);
        #pragma unroll
        for (int mt = 0; mt < 2; mt++)
            #pragma unroll
            for (int nt = 0; nt < 8; nt++)
                mma_bf16(cacc[mt][nt], ah[mt], bl[nt]);
        #pragma unroll
        for (int mt = 0; mt < 2; mt++)
            #pragma unroll
            for (int nt = 0; nt < 8; nt++)
                mma_bf16(cacc[mt][nt], ah[mt], bh[nt]);
        __syncthreads();
    }

    // ---- epilogue ----
    #pragma unroll
    for (int mt = 0; mt < 2; mt++) {
        #pragma unroll
        for (int half = 0; half < 2; half++) {
            int r  = wm*32 + mt*16 + gid + half*8;
            int gm = m_base + r;
            float gate = 1.f;
            if (mode == GM_MOE_DOWN) gate = g_assign_gate[gm];
            #pragma unroll
            for (int nt = 0; nt < 8; nt++) {
                int c = n_base + wn*64 + nt*8 + tig*2;
                float v0 = cacc[mt][nt][half*2 + 0] + bias[c];
                float v1 = cacc[mt][nt][half*2 + 1] + bias[c + 1];
                if (mode == GM_PATCH) {
                    v0 += extra[(size_t)(gm & 255)*N + c];
                    v1 += extra[(size_t)(gm & 255)*N + c + 1];
                    *(float2*)&outF[(size_t)gm*N + c] = make_float2(v0, v1);
                } else if (mode == GM_RES) {
                    v0 += extra[(size_t)gm*N + c];
                    v1 += extra[(size_t)gm*N + c + 1];
                    *(float2*)&outF[(size_t)gm*N + c] = make_float2(v0, v1);
                } else if (mode == GM_MOE_UP) {
                    v0 = 0.5f*v0*(1.f + erff(v0*0.70710678118654752f));
                    v1 = 0.5f*v1*(1.f + erff(v1*0.70710678118654752f));
                    __nv_bfloat162 hp = __floats2bfloat162_rn(v0, v1);
                    __nv_bfloat162 lp = __floats2bfloat162_rn(v0 - __low2float(hp),
                                                              v1 - __high2float(hp));
                    *(__nv_bfloat162*)(outH + (size_t)gm*N + c) = hp;
                    *(__nv_bfloat162*)(outL + (size_t)gm*N + c) = lp;
                } else if (mode == GM_MOE_DOWN) {
                    *(float2*)&outF[(size_t)gm*N + c] = make_float2(v0*gate, v1*gate);
                } else {
                    *(float2*)&outF[(size_t)gm*N + c] = make_float2(v0, v1);
                }
            }
        }
    }
}

// ---------------- 1-pass tf32 GEMM (MoE2: smooth-only downstream) ----------------
__global__ void __launch_bounds__(256)
gemm_tf32_kernel(const float* __restrict__ A, const float* __restrict__ Bbase,
                 const float* __restrict__ biasbase, const float* __restrict__ extra,
                 float* __restrict__ Cout, int N, int K, int mode)
{
    int tileY = blockIdx.y;
    const float* B = Bbase;
    const float* bias = biasbase;
    if (mode == GM_MOE_UP || mode == GM_MOE_DOWN) {
        int expert = g_tile_expert[tileY];
        if (expert < 0) return;
        B    = Bbase    + (size_t)expert * K * N;
        bias = biasbase + (size_t)expert * N;
    }

    __shared__ float As[2][128][20];
    __shared__ float Bs[2][16][136];

    int tid = threadIdx.x;
    int m_base = tileY * 128;
    int n_base = blockIdx.x * 128;

    int rA = tid >> 2, cA = (tid & 3) * 4;
    const float* aptr0; const float* aptr1;
    bool av0 = true, av1 = true;
    if (mode == GM_MOE_UP) {
        int t0 = g_assign_token[m_base + rA];
        int t1 = g_assign_token[m_base + rA + 64];
        av0 = (t0 >= 0); av1 = (t1 >= 0);
        aptr0 = A + (size_t)(av0 ? t0 : 0) * K + cA;
        aptr1 = A + (size_t)(av1 ? t1 : 0) * K + cA;
    } else {
        aptr0 = A + (size_t)(m_base + rA) * K + cA;
        aptr1 = A + (size_t)(m_base + rA + 64) * K + cA;
    }
    int rB = tid >> 5;
    int cB = (tid & 31) * 4;
    const float* bptr0 = B + (size_t)rB * N + n_base + cB;
    const float* bptr1 = B + (size_t)(rB + 8) * N + n_base + cB;

    uint32_t sA0[2], sA1[2], sB0[2], sB1[2];
    #pragma unroll
    for (int bf = 0; bf < 2; bf++) {
        sA0[bf] = smem_u32(&As[bf][rA][cA]);
        sA1[bf] = smem_u32(&As[bf][rA + 64][cA]);
        sB0[bf] = smem_u32(&Bs[bf][rB][cB]);
        sB1[bf] = smem_u32(&Bs[bf][rB + 8][cB]);
    }

    int lane = tid & 31, warp = tid >> 5;
    int wm = warp >> 1, wn = warp & 1;
    int gid = lane >> 2, tig = lane & 3;

    float cacc[2][8][4];
    #pragma unroll
    for (int mt = 0; mt < 2; mt++)
        #pragma unroll
        for (int nt = 0; nt < 8; nt++)
            #pragma unroll
            for (int q = 0; q < 4; q++) cacc[mt][nt][q] = 0.f;

    int KT = (K + 15) / 16;

    {
        int k0 = 0, bf = 0;
        cp_async16(sA0[bf], aptr0 + k0, (av0 && k0 + cA < K) ? 16 : 0);
        cp_async16(sA1[bf], aptr1 + k0, (av1 && k0 + cA < K) ? 16 : 0);
        cp_async16(sB0[bf], bptr0 + (size_t)k0 * N, (k0 + rB < K) ? 16 : 0);
        cp_async16(sB1[bf], bptr1 + (size_t)k0 * N, (k0 + rB + 8 < K) ? 16 : 0);
        cp_commit();
    }

    for (int it = 0; it < KT; ++it) {
        if (it + 1 < KT) {
            int k0 = (it + 1) * 16, bf = (it + 1) & 1;
            cp_async16(sA0[bf], aptr0 + k0, (av0 && k0 + cA < K) ? 16 : 0);
            cp_async16(sA1[bf], aptr1 + k0, (av1 && k0 + cA < K) ? 16 : 0);
            cp_async16(sB0[bf], bptr0 + (size_t)k0 * N, (k0 + rB < K) ? 16 : 0);
            cp_async16(sB1[bf], bptr1 + (size_t)k0 * N, (k0 + rB + 8 < K) ? 16 : 0);
            cp_commit();
            cp_wait1();
        } else {
            cp_wait0();
        }
        __syncthreads();

        int buf = it & 1;
        #pragma unroll
        for (int ks = 0; ks < 16; ks += 8) {
            uint32_t ah[2][4];
            #pragma unroll
            for (int mt = 0; mt < 2; mt++) {
                int mr = wm*32 + mt*16 + gid;
                ah[mt][0] = cvt_tf32(As[buf][mr    ][ks + tig    ]);
                ah[mt][1] = cvt_tf32(As[buf][mr + 8][ks + tig    ]);
                ah[mt][2] = cvt_tf32(As[buf][mr    ][ks + tig + 4]);
                ah[mt][3] = cvt_tf32(As[buf][mr + 8][ks + tig + 4]);
            }
            uint32_t bh[8][2];
            #pragma unroll
            for (int nt = 0; nt < 8; nt++) {
                int nc = wn*64 + nt*8 + gid;
                bh[nt][0] = cvt_tf32(Bs[buf][ks + tig    ][nc]);
                bh[nt][1] = cvt_tf32(Bs[buf][ks + tig + 4][nc]);
            }
            #pragma unroll
            for (int mt = 0; mt < 2; mt++)
                #pragma unroll
                for (int nt = 0; nt < 8; nt++)
                    mma_tf32(cacc[mt][nt], ah[mt], bh[nt]);
        }
        __syncthreads();
    }

    #pragma unroll
    for (int mt = 0; mt < 2; mt++) {
        #pragma unroll
        for (int half = 0; half < 2; half++) {
            int r  = wm*32 + mt*16 + gid + half*8;
            int gm = m_base + r;
            float gate = 1.f;
            if (mode == GM_MOE_DOWN) gate = g_assign_gate[gm];
            #pragma unroll
            for (int nt = 0; nt < 8; nt++) {
                int c = n_base + wn*64 + nt*8 + tig*2;
                float v0 = cacc[mt][nt][half*2 + 0] + bias[c];
                float v1 = cacc[mt][nt][half*2 + 1] + bias[c + 1];
                if (mode == GM_MOE_UP) {
                    v0 = 0.5f*v0*(1.f + erff(v0*0.70710678118654752f));
                    v1 = 0.5f*v1*(1.f + erff(v1*0.70710678118654752f));
                } else if (mode == GM_MOE_DOWN) {
                    v0 *= gate; v1 *= gate;
                }
                *(float2*)&Cout[(size_t)gm*N + c] = make_float2(v0, v1);
            }
        }
    }
}

// ---------------- attention ----------------
__global__ void __launch_bounds__(256)
scores_kernel() {
    int bh = blockIdx.z;
    int b = bh >> 3, h = bh & 7;
    const float* Q = g_q  + (size_t)(b*SEQ)*DIM + h*HD;
    const float* K = g_kk + (size_t)(b*SEQ)*DIM + h*HD;
    __shared__ float Qs[64][65], Ks[64][65];
    int tid = threadIdx.x;
    int i0 = blockIdx.x * 64, j0 = blockIdx.y * 64;
    for (int idx = tid; idx < 64*64; idx += 256) {
        int r = idx >> 6, c = idx & 63;
        Qs[r][c] = Q[(size_t)(i0+r)*DIM + c];
        Ks[r][c] = K[(size_t)(j0+r)*DIM + c];
    }
    __syncthreads();
    int ty = tid >> 4, tx = tid & 15;
    float acc[4][4] = {};
    #pragma unroll 8
    for (int kx = 0; kx < 64; kx++) {
        float a[4], bb[4];
        #pragma unroll
        for (int i = 0; i < 4; i++) a[i]  = Qs[ty*4+i][kx];
        #pragma unroll
        for (int j = 0; j < 4; j++) bb[j] = Ks[tx*4+j][kx];
        #pragma unroll
        for (int i = 0; i < 4; i++)
            #pragma unroll
            for (int j = 0; j < 4; j++)
                acc[i][j] += a[i]*bb[j];
    }
    float* Cp = g_attn + (size_t)bh*SEQ*SEQ;
    #pragma unroll
    for (int i = 0; i < 4; i++)
        #pragma unroll
        for (int j = 0; j < 4; j++)
            Cp[(size_t)(i0+ty*4+i)*SEQ + (j0+tx*4+j)] = acc[i][j] * 0.125f;
}

__global__ void softmax256_kernel() {
    float* row = g_attn + (size_t)blockIdx.x * 256;
    int t = threadIdx.x;
    float v = row[t];
    __shared__ float red[256];
    red[t] = v; __syncthreads();
    for (int s = 128; s; s >>= 1) { if (t < s) red[t] = fmaxf(red[t], red[t+s]); __syncthreads(); }
    float mx = red[0]; __syncthreads();
    float e = expf(v - mx);
    red[t] = e; __syncthreads();
    for (int s = 128; s; s >>= 1) { if (t < s) red[t] += red[t+s]; __syncthreads(); }
    row[t] = e / red[0];
}

__global__ void attn_mean_sm_kernel(float* __restrict__ out) {
    int bs = blockIdx.x;
    int b = bs >> 8, srow = bs & 255;
    int j = threadIdx.x;
    float v = 0.f;
    #pragma unroll
    for (int h = 0; h < NHEAD; h++)
        v += g_attn[((size_t)(b*NHEAD + h)*SEQ + srow)*SEQ + j];
    v *= (1.f / NHEAD);
    __shared__ float red[256];
    red[j] = v; __syncthreads();
    for (int s = 128; s; s >>= 1) { if (j < s) red[j] = fmaxf(red[j], red[j+s]); __syncthreads(); }
    float mx = red[0]; __syncthreads();
    float e = expf(v - mx);
    red[j] = e; __syncthreads();
    for (int s = 128; s; s >>= 1) { if (j < s) red[j] += red[j+s]; __syncthreads(); }
    out[(size_t)bs*256 + j] = e / red[0];
}

__global__ void __launch_bounds__(256)
attnv_kernel() {
    int bh = blockIdx.z;
    int b = bh >> 3, h = bh & 7;
    const float* Ap = g_attn + (size_t)bh*SEQ*SEQ;
    const float* V  = g_v + (size_t)(b*SEQ)*DIM + h*HD;
    int i0 = blockIdx.x * 64;
    __shared__ float As[64][65], Vs[64][65];
    int tid = threadIdx.x;
    int ty = tid >> 4, tx = tid & 15;
    float acc[4][4] = {};
    for (int c0 = 0; c0 < SEQ; c0 += 64) {
        for (int idx = tid; idx < 64*64; idx += 256) {
            int r = idx >> 6, c = idx & 63;
            As[r][c] = Ap[(size_t)(i0+r)*SEQ + c0 + c];
            Vs[r][c] = V[(size_t)(c0+r)*DIM + c];
        }
        __syncthreads();
        #pragma unroll 8
        for (int kx = 0; kx < 64; kx++) {
            float a[4], bb[4];
            #pragma unroll
            for (int i = 0; i < 4; i++) a[i]  = As[ty*4+i][kx];
            #pragma unroll
            for (int j = 0; j < 4; j++) bb[j] = Vs[kx][tx*4+j];
            #pragma unroll
            for (int i = 0; i < 4; i++)
                #pragma unroll
                for (int j = 0; j < 4; j++)
                    acc[i][j] += a[i]*bb[j];
        }
        __syncthreads();
    }
    // write bf16 hi/lo planes (proj GEMM input)
    #pragma unroll
    for (int i = 0; i < 4; i++) {
        size_t base = (size_t)(b*SEQ + i0 + ty*4 + i)*DIM + h*HD + tx*4;
        #pragma unroll
        for (int j = 0; j < 4; j += 2) {
            float v0 = acc[i][j], v1 = acc[i][j+1];
            __nv_bfloat162 hp = __floats2bfloat162_rn(v0, v1);
            __nv_bfloat162 lp = __floats2bfloat162_rn(v0 - __low2float(hp),
                                                      v1 - __high2float(hp));
            *(__nv_bfloat162*)(g_att_h + base + j) = hp;
            *(__nv_bfloat162*)(g_att_l + base + j) = lp;
        }
    }
}

// ---------------- MoE routing ----------------
__global__ void moe_reset_kernel() {
    int idx = blockIdx.x * 256 + threadIdx.x;
    if (idx < ACAP) g_assign_token[idx] = -1;
    if (idx < NEXP) { g_counts[idx] = 0; g_fill[idx] = 0; g_probsum[idx] = 0.f; }
}

__global__ void router_kernel(const float* __restrict__ x, const float* __restrict__ rw,
                              const float* __restrict__ rb) {
    __shared__ float s_ps[NEXP];
    __shared__ int   s_cnt[NEXP];
    int t = threadIdx.x;
    if (t < NEXP) { s_ps[t] = 0.f; s_cnt[t] = 0; }
    __syncthreads();
    int warp = t >> 5, lane = t & 31;
    int token = blockIdx.x * 8 + warp;
    float acc[NEXP] = {};
    const float* xr = x + (size_t)token * DIM;
    for (int kx = lane; kx < DIM; kx += 32) {
        float xv = xr[kx];
        const float* rr = rw + (size_t)kx * NEXP;
        #pragma unroll
        for (int e = 0; e < NEXP; e++) acc[e] += xv * rr[e];
    }
    #pragma unroll
    for (int e = 0; e < NEXP; e++)
        #pragma unroll
        for (int o = 16; o; o >>= 1)
            acc[e] += __shfl_down_sync(0xffffffffu, acc[e], o);
    if (lane == 0) {
        float p[NEXP], mx = -1e30f;
        #pragma unroll
        for (int e = 0; e < NEXP; e++) { acc[e] += rb[e]; mx = fmaxf(mx, acc[e]); }
        float sum = 0.f;
        #pragma unroll
        for (int e = 0; e < NEXP; e++) { p[e] = expf(acc[e] - mx); sum += p[e]; }
        float inv = 1.f / sum;
        #pragma unroll
        for (int e = 0; e < NEXP; e++) p[e] *= inv;
        int i1 = 0;
        #pragma unroll
        for (int e = 1; e < NEXP; e++) if (p[e] > p[i1]) i1 = e;
        int i2 = (i1 == 0) ? 1 : 0;
        #pragma unroll
        for (int e = 0; e < NEXP; e++) if (e != i1 && p[e] > p[i2]) i2 = e;
        g_topi[token*2]   = i1; g_topv[token*2]   = p[i1];
        g_topi[token*2+1] = i2; g_topv[token*2+1] = p[i2];
        atomicAdd(&s_cnt[i1], 1);
        atomicAdd(&s_cnt[i2], 1);
        #pragma unroll
        for (int e = 0; e < NEXP; e++) atomicAdd(&s_ps[e], p[e]);
    }
    __syncthreads();
    if (t < NEXP) {
        atomicAdd(&g_counts[t], s_cnt[t]);
        atomicAdd(&g_probsum[t], s_ps[t]);
    }
}

__global__ void loss_accum_kernel() {
    float L = 0.f;
    for (int e = 0; e < NEXP; e++)
        L += ((float)g_counts[e] / (float)TOK) * (g_probsum[e] / (float)TOK);
    g_loss[0] += (float)NEXP * L;
}

__global__ void bucket_prep_kernel() {
    if (threadIdx.x == 0) {
        int off = 0;
        for (int e = 0; e < NEXP; e++) {
            g_off[e] = off;
            off += ((g_counts[e] + 127) >> 7) << 7;
        }
        g_off[NEXP] = off;
    }
    __syncthreads();
    for (int tix = threadIdx.x; tix < MAXT; tix += blockDim.x) {
        int e = -1;
        for (int q = 0; q < NEXP; q++)
            if (tix*128 >= g_off[q] && tix*128 < g_off[q+1]) e = q;
        g_tile_expert[tix] = e;
    }
}

__global__ void scatter_kernel() {
    int token = blockIdx.x * 256 + threadIdx.x;
    if (token >= TOK) return;
    #pragma unroll
    for (int kk = 0; kk < 2; kk++) {
        int e = g_topi[token*2 + kk];
        int p = atomicAdd(&g_fill[e], 1);
        int slot = g_off[e] + p;
        g_assign_token[slot] = token;
        g_assign_gate[slot]  = g_topv[token*2 + kk];
        g_token_slot[token*2 + kk] = slot;
    }
}

__global__ void moe_combine_kernel(float* __restrict__ o) {
    int i = blockIdx.x * 256 + threadIdx.x;
    int token = i >> 9, d = i & 511;
    int s0 = g_token_slot[token*2], s1 = g_token_slot[token*2 + 1];
    o[i] = g_contrib[(size_t)s0*DIM + d] + g_contrib[(size_t)s1*DIM + d];
}

// ---------------- head ----------------
__global__ void fv_kernel(const float* __restrict__ o2, float* __restrict__ out_fv) {
    int b = blockIdx.x, d = threadIdx.x;
    float s = 0.f;
    for (int t = 0; t < SEQ; t++)
        s += o2[(size_t)(b*SEQ + t)*DIM + d];
    float v = s * (1.f / SEQ);
    out_fv[b*DIM + d] = v;
    g_fv[b*DIM + d] = v;
}

__global__ void logits_kernel(const float* __restrict__ cw, const float* __restrict__ cb,
                              float* __restrict__ out) {
    __shared__ float xf[DIM];
    int b = blockIdx.x, t = threadIdx.x;
    xf[t] = g_fv[b*DIM + t];
    __syncthreads();
    float acc = 0.f;
    for (int kx = 0; kx < DIM; kx++)
        acc += xf[kx] * cw[(size_t)kx*DIM + t];
    out[b*DIM + t] = acc + cb[t];
}

__global__ void loss_write_kernel(float* __restrict__ dst) { dst[0] = g_loss[0]; }

// ---------------- host ----------------
static void moe_route(const float* xfp, const float* rw, const float* rb) {
    moe_reset_kernel<<<(ACAP + 255)/256, 256>>>();
    router_kernel<<<TOK/8, 256>>>(xfp, rw, rb);
    loss_accum_kernel<<<1, 1>>>();
    bucket_prep_kernel<<<1, 64>>>();
    scatter_kernel<<<TOK/256, 256>>>();
}

extern "C" void kernel_launch(void* const* d_in, const int* in_sizes, int n_in,
                              void* d_out, int out_size) {
    const float* x     = (const float*)d_in[0];
    const float* pe_w  = (const float*)d_in[1];
    const float* pe_b  = (const float*)d_in[2];
    const float* pos   = (const float*)d_in[3];
    const float* ln1_g = (const float*)d_in[4];
    const float* ln1_b = (const float*)d_in[5];
    const float* ln2_g = (const float*)d_in[6];
    const float* ln2_b = (const float*)d_in[7];
    const float* ln3_g = (const float*)d_in[8];
    const float* ln3_b = (const float*)d_in[9];
    const float* wq = (const float*)d_in[10];
    const float* bq = (const float*)d_in[11];
    const float* wk = (const float*)d_in[12];
    const float* bk = (const float*)d_in[13];
    const float* wv = (const float*)d_in[14];
    const float* bv = (const float*)d_in[15];
    const float* wo = (const float*)d_in[16];
    const float* bo = (const float*)d_in[17];
    const float* m1_rw = (const float*)d_in[18];
    const float* m1_rb = (const float*)d_in[19];
    const float* m1_w1 = (const float*)d_in[20];
    const float* m1_b1 = (const float*)d_in[21];
    const float* m1_w2 = (const float*)d_in[22];
    const float* m1_b2 = (const float*)d_in[23];
    const float* m2_rw = (const float*)d_in[24];
    const float* m2_rb = (const float*)d_in[25];
    const float* m2_w1 = (const float*)d_in[26];
    const float* m2_b1 = (const float*)d_in[27];
    const float* m2_w2 = (const float*)d_in[28];
    const float* m2_b2 = (const float*)d_in[29];
    const float* cls_w = (const float*)d_in[30];
    const float* cls_b = (const float*)d_in[31];
    float* out = (float*)d_out;

    float *p_e, *p_xln, *p_q, *p_k, *p_v, *p_e2, *p_o1, *p_o2, *p_hidden, *p_contrib;
    __nv_bfloat16 *p_path, *p_patl, *p_xh, *p_xl, *p_ath, *p_atl, *p_hh, *p_hl;
    __nv_bfloat16 *p_peTh, *p_peTl, *p_wqTh, *p_wqTl, *p_wkTh, *p_wkTl,
                  *p_wvTh, *p_wvTl, *p_woTh, *p_woTl,
                  *p_m1w1h, *p_m1w1l, *p_m1w2h, *p_m1w2l;
    cudaGetSymbolAddress((void**)&p_path,   g_pat_h);
    cudaGetSymbolAddress((void**)&p_patl,   g_pat_l);
    cudaGetSymbolAddress((void**)&p_e,      g_e);
    cudaGetSymbolAddress((void**)&p_xln,    g_xln);
    cudaGetSymbolAddress((void**)&p_xh,     g_xln_h);
    cudaGetSymbolAddress((void**)&p_xl,     g_xln_l);
    cudaGetSymbolAddress((void**)&p_q,      g_q);
    cudaGetSymbolAddress((void**)&p_k,      g_kk);
    cudaGetSymbolAddress((void**)&p_v,      g_v);
    cudaGetSymbolAddress((void**)&p_ath,    g_att_h);
    cudaGetSymbolAddress((void**)&p_atl,    g_att_l);
    cudaGetSymbolAddress((void**)&p_e2,     g_e2);
    cudaGetSymbolAddress((void**)&p_o1,     g_o1);
    cudaGetSymbolAddress((void**)&p_o2,     g_o2);
    cudaGetSymbolAddress((void**)&p_hidden, g_hidden);
    cudaGetSymbolAddress((void**)&p_hh,     g_hid_h);
    cudaGetSymbolAddress((void**)&p_hl,     g_hid_l);
    cudaGetSymbolAddress((void**)&p_contrib,g_contrib);
    cudaGetSymbolAddress((void**)&p_peTh,   g_peT_h);
    cudaGetSymbolAddress((void**)&p_peTl,   g_peT_l);
    cudaGetSymbolAddress((void**)&p_wqTh,   g_wqT_h);
    cudaGetSymbolAddress((void**)&p_wqTl,   g_wqT_l);
    cudaGetSymbolAddress((void**)&p_wkTh,   g_wkT_h);
    cudaGetSymbolAddress((void**)&p_wkTl,   g_wkT_l);
    cudaGetSymbolAddress((void**)&p_wvTh,   g_wvT_h);
    cudaGetSymbolAddress((void**)&p_wvTl,   g_wvT_l);
    cudaGetSymbolAddress((void**)&p_woTh,   g_woT_h);
    cudaGetSymbolAddress((void**)&p_woTl,   g_woT_l);
    cudaGetSymbolAddress((void**)&p_m1w1h,  g_m1w1T_h);
    cudaGetSymbolAddress((void**)&p_m1w1l,  g_m1w1T_l);
    cudaGetSymbolAddress((void**)&p_m1w2h,  g_m1w2T_h);
    cudaGetSymbolAddress((void**)&p_m1w2l,  g_m1w2T_l);

    zero_loss_kernel<<<1, 1>>>();

    // ---- weight conversions (transpose + bf16 hi/lo split), once per launch ----
    wconv_kernel<<<dim3(DIM/32, (PDP+31)/32, 1), 256>>>(pe_w, p_peTh, p_peTl, PD, DIM, PDP);
    wconv_kernel<<<dim3(DIM/32, DIM/32, 1), 256>>>(wq, p_wqTh, p_wqTl, DIM, DIM, DIM);
    wconv_kernel<<<dim3(DIM/32, DIM/32, 1), 256>>>(wk, p_wkTh, p_wkTl, DIM, DIM, DIM);
    wconv_kernel<<<dim3(DIM/32, DIM/32, 1), 256>>>(wv, p_wvTh, p_wvTl, DIM, DIM, DIM);
    wconv_kernel<<<dim3(DIM/32, DIM/32, 1), 256>>>(wo, p_woTh, p_woTl, DIM, DIM, DIM);
    wconv_kernel<<<dim3(HID/32, DIM/32, NEXP), 256>>>(m1_w1, p_m1w1h, p_m1w1l, DIM, HID, DIM);
    wconv_kernel<<<dim3(DIM/32, HID/32, NEXP), 256>>>(m1_w2, p_m1w2h, p_m1w2l, HID, DIM, HID);

    // ---- patch embed:  e = patches @ pe_w + pe_b + pos ----
    patch_kernel<<<((size_t)TOK*PDP + 255)/256, 256>>>(x);
    dim3 gD(DIM/128, TOK/128);
    gemm_bf16p_kernel<<<gD, 256>>>(p_path, p_patl, p_peTh, p_peTl, pe_b, pos,
                                   p_e, nullptr, nullptr, DIM, PDP, GM_PATCH);

    // ---- attention ----
    ln_kernel<<<TOK, 256>>>(p_e, ln1_g, ln1_b, p_xln, p_xh, p_xl);
    gemm_bf16p_kernel<<<gD, 256>>>(p_xh, p_xl, p_wqTh, p_wqTl, bq, nullptr,
                                   p_q, nullptr, nullptr, DIM, DIM, GM_BIAS);
    gemm_bf16p_kernel<<<gD, 256>>>(p_xh, p_xl, p_wkTh, p_wkTl, bk, nullptr,
                                   p_k, nullptr, nullptr, DIM, DIM, GM_BIAS);
    gemm_bf16p_kernel<<<gD, 256>>>(p_xh, p_xl, p_wvTh, p_wvTl, bv, nullptr,
                                   p_v, nullptr, nullptr, DIM, DIM, GM_BIAS);
    scores_kernel<<<dim3(4, 4, BATCH*NHEAD), 256>>>();
    softmax256_kernel<<<BATCH*NHEAD*SEQ, 256>>>();
    attn_mean_sm_kernel<<<TOK, 256>>>(out + OFF_ATTN);
    attnv_kernel<<<dim3(4, 1, BATCH*NHEAD), 256>>>();
    gemm_bf16p_kernel<<<gD, 256>>>(p_ath, p_atl, p_woTh, p_woTl, bo, p_e,
                                   p_e2, nullptr, nullptr, DIM, DIM, GM_RES);

    // ---- MoE 1 (feeds MoE2's router -> precise bf16x3 on pre-split planes) ----
    ln_kernel<<<TOK, 256>>>(p_e2, ln2_g, ln2_b, p_xln, p_xh, p_xl);
    moe_route(p_xln, m1_rw, m1_rb);
    gemm_bf16p_kernel<<<dim3(HID/128, MAXT), 256>>>(p_xh, p_xl, p_m1w1h, p_m1w1l, m1_b1,
                                                    nullptr, nullptr, p_hh, p_hl,
                                                    HID, DIM, GM_MOE_UP);
    gemm_bf16p_kernel<<<dim3(DIM/128, MAXT), 256>>>(p_hh, p_hl, p_m1w2h, p_m1w2l, m1_b2,
                                                    nullptr, p_contrib, nullptr, nullptr,
                                                    DIM, HID, GM_MOE_DOWN);
    moe_combine_kernel<<<TOK*DIM/256, 256>>>(p_o1);

    // ---- MoE 2 (feeds only smooth ops -> fast single-pass tf32, fp32 inputs) ----
    ln_kernel<<<TOK, 256>>>(p_o1, ln3_g, ln3_b, p_xln, nullptr, nullptr);
    moe_route(p_xln, m2_rw, m2_rb);
    gemm_tf32_kernel<<<dim3(HID/128, MAXT), 256>>>(p_xln, m2_w1, m2_b1, nullptr,
                                                   p_hidden, HID, DIM, GM_MOE_UP);
    gemm_tf32_kernel<<<dim3(DIM/128, MAXT), 256>>>(p_hidden, m2_w2, m2_b2, nullptr,
                                                   p_contrib, DIM, HID, GM_MOE_DOWN);
    moe_combine_kernel<<<TOK*DIM/256, 256>>>(p_o2);

    // ---- head ----
    fv_kernel<<<BATCH, 512>>>(p_o2, out + OFF_FV);
    logits_kernel<<<BATCH, 512>>>(cls_w, cls_b, out);
    loss_write_kernel<<<1, 1>>>(out + OFF_LOSS);

    (void)in_sizes; (void)n_in; (void)out_size;
}